// round 5
// baseline (speedup 1.0000x reference)
#include <cuda_runtime.h>
#include <cuda_bf16.h>
#include <cstdint>

// ---------------------------------------------------------------------------
// Problem constants
// ---------------------------------------------------------------------------
#define BATCH   2
#define SEQ     2048
#define DMODEL  1024
#define DINNER  2048
#define DSTATE  16
#define DCONV   4
#define DTRANK  64
#define MROWS   (BATCH * SEQ)          // 4096
#define XZCOLS  (2 * DINNER)           // 4096
#define XDBLC   (DTRANK + 2 * DSTATE)  // 96
#define XSPLITK 4

// ---------------------------------------------------------------------------
// Scratch (device globals; no runtime allocation allowed)
// ---------------------------------------------------------------------------
__device__ float g_xz    [(size_t)MROWS * XZCOLS];   // [xi | z]
__device__ float g_xc    [(size_t)MROWS * DINNER];   // conv+silu (full fp32)
__device__ float g_xc_r  [(size_t)MROWS * DINNER];   // tf32-rounded copy
__device__ float g_xdbl  [(size_t)MROWS * XDBLC];    // [dt_r | B | C] full
__device__ float g_xdbl_r[(size_t)MROWS * XDBLC];    // tf32-rounded copy
__device__ float g_xpart [(size_t)XSPLITK * MROWS * XDBLC];
__device__ float g_dt    [(size_t)MROWS * DINNER];   // softplus(dt), full
__device__ float g_y     [(size_t)MROWS * DINNER];   // scan out (tf32-rounded)
__device__ float g_h     [(size_t)MROWS * DMODEL];   // out_proj + residual
// tf32-rounded inputs
__device__ float g_x_r   [(size_t)MROWS * DMODEL];
__device__ float g_win_r [(size_t)XZCOLS * DMODEL];
__device__ float g_wout_r[(size_t)DMODEL * DINNER];
__device__ float g_wx_r  [(size_t)XDBLC * DINNER];
__device__ float g_wdt_r [(size_t)DINNER * DTRANK];

enum { EPI_PLAIN = 0, EPI_SOFTPLUS = 1, EPI_RES = 2 };

// ---------------------------------------------------------------------------
// PTX helpers
// ---------------------------------------------------------------------------
__device__ __forceinline__ uint32_t f2tf32(float f) {
    uint32_t r;
    asm("cvt.rna.tf32.f32 %0, %1;" : "=r"(r) : "f"(f));
    return r;
}
__device__ __forceinline__ float rtf(float f) { return __uint_as_float(f2tf32(f)); }

__device__ __forceinline__ void cp_async16(uint32_t dst, const void* src) {
    asm volatile("cp.async.cg.shared.global [%0], [%1], 16;\n" :: "r"(dst), "l"(src));
}
__device__ __forceinline__ void cp_commit() {
    asm volatile("cp.async.commit_group;\n" ::: "memory");
}
template <int N> __device__ __forceinline__ void cp_wait() {
    asm volatile("cp.async.wait_group %0;\n" :: "n"(N) : "memory");
}
__device__ __forceinline__ void ldsm_x4(uint32_t& r0, uint32_t& r1,
                                        uint32_t& r2, uint32_t& r3, uint32_t addr) {
    asm volatile("ldmatrix.sync.aligned.m8n8.x4.shared.b16 {%0,%1,%2,%3}, [%4];\n"
                 : "=r"(r0), "=r"(r1), "=r"(r2), "=r"(r3) : "r"(addr));
}

// ---------------------------------------------------------------------------
// tf32 rounding copy kernel (float4 granularity; n4 = element_count/4)
// ---------------------------------------------------------------------------
__global__ __launch_bounds__(256)
void round_tf32_kernel(const float4* __restrict__ src, float4* __restrict__ dst, int n4)
{
    int i = blockIdx.x * 256 + threadIdx.x;
    if (i >= n4) return;
    float4 v = src[i];
    v.x = rtf(v.x); v.y = rtf(v.y); v.z = rtf(v.z); v.w = rtf(v.w);
    dst[i] = v;
}

// ---------------------------------------------------------------------------
// Tensor-core NT GEMM (tf32): C[M,N] = A[M,K]*B[N,K]^T, row-major.
// BM=128, BN in {128,256}, BK=32. cp.async 3-stage, SW128 swizzle, ldmatrix.
// 256 threads = 8 warps. BN=128: 4m x 2n warps (32x64). BN=256: 2m x 4n (64x64).
// Inputs must already be tf32-rounded. blockIdx.z: k-slice.
// ---------------------------------------------------------------------------
#define GSTAGES 3

template <int EPI, int BN>
__global__ __launch_bounds__(256)
void mma_gemm_nt(const float* __restrict__ A, int lda,
                 const float* __restrict__ B, int ldb,
                 float* __restrict__ C, int ldc,
                 int K, int N, const float* __restrict__ aux,
                 int kz, size_t cz)
{
    constexpr int NWARP_M = (BN == 256) ? 2 : 4;
    constexpr int NWARP_N = 8 / NWARP_M;
    constexpr int WT_M = 128 / NWARP_M;      // 64 or 32
    constexpr int WT_N = BN / NWARP_N;       // 64
    constexpr int MI = WT_M / 16;            // 4 or 2
    constexpr int NJ = WT_N / 8;             // 8
    constexpr int A_BYTES = 128 * 32 * 4;    // 16 KB
    constexpr int B_BYTES = BN * 32 * 4;     // 16/32 KB
    constexpr int BCH = BN * 8 / 256;        // B chunks per thread (4/8)

    extern __shared__ __align__(16) char smem[];
    const uint32_t smem_u = (uint32_t)__cvta_generic_to_shared(smem);
    const uint32_t smA = smem_u;
    const uint32_t smB = smem_u + GSTAGES * A_BYTES;

    A += (size_t)blockIdx.z * kz;
    B += (size_t)blockIdx.z * kz;
    C += (size_t)blockIdx.z * cz;

    const int tid  = threadIdx.x;
    const int lane = tid & 31;
    const int wid  = tid >> 5;
    const int g    = lane >> 2;
    const int tig  = lane & 3;
    const int wm   = wid % NWARP_M;
    const int wn   = wid / NWARP_M;
    const int m0   = blockIdx.y * 128;
    const int n0   = blockIdx.x * BN;

    // --- cp.async source pointers / swizzled dst offsets ---
    const float* asrc[4];
    uint32_t aoff[4];
#pragma unroll
    for (int i = 0; i < 4; i++) {
        int id = tid + i * 256;
        int r  = id >> 3;
        int ch = id & 7;
        aoff[i] = (uint32_t)((r * 128 + ch * 16) ^ ((r & 7) << 4));
        asrc[i] = A + (size_t)(m0 + r) * lda + ch * 4;
    }
    const float* bsrc[BCH];
    uint32_t boff[BCH];
#pragma unroll
    for (int i = 0; i < BCH; i++) {
        int id = tid + i * 256;
        int r  = id >> 3;
        int ch = id & 7;
        boff[i] = (uint32_t)((r * 128 + ch * 16) ^ ((r & 7) << 4));
        int br = n0 + r; if (br > N - 1) br = N - 1;
        bsrc[i] = B + (size_t)br * ldb + ch * 4;
    }

    // --- ldmatrix addressing ---
    const int lrow  = (lane & 7) + ((lane >> 3) & 1) * 8;
    const int lkb   = ((lane >> 4) & 1) * 16;
    const uint32_t lmask = (uint32_t)((lane & 7) << 4);
    uint32_t abase[MI], bbase[NJ / 2];
#pragma unroll
    for (int mi = 0; mi < MI; mi++)
        abase[mi] = (uint32_t)((wm * WT_M + mi * 16 + lrow) * 128 + lkb);
#pragma unroll
    for (int p = 0; p < NJ / 2; p++)
        bbase[p] = (uint32_t)((wn * WT_N + p * 16 + lrow) * 128 + lkb);

    float acc[MI][NJ][4];
#pragma unroll
    for (int mi = 0; mi < MI; mi++)
#pragma unroll
        for (int nj = 0; nj < NJ; nj++)
#pragma unroll
            for (int q = 0; q < 4; q++) acc[mi][nj][q] = 0.f;

    const int NK = K / 32;

    auto issue = [&](int t) {
        const int s = t % GSTAGES;
        const uint32_t sa = smA + s * A_BYTES;
        const uint32_t sb = smB + s * B_BYTES;
        const int k0 = t * 32;
#pragma unroll
        for (int i = 0; i < 4; i++) cp_async16(sa + aoff[i], asrc[i] + k0);
#pragma unroll
        for (int i = 0; i < BCH; i++) cp_async16(sb + boff[i], bsrc[i] + k0);
    };

    issue(0); cp_commit();
    if (NK > 1) issue(1);
    cp_commit();
    cp_wait<1>();
    __syncthreads();

    for (int t = 0; t < NK; t++) {
        const int s = t % GSTAGES;
        const uint32_t sa = smA + s * A_BYTES;
        const uint32_t sb = smB + s * B_BYTES;

#pragma unroll
        for (int kg = 0; kg < 4; kg++) {
            uint32_t af[MI][4];
#pragma unroll
            for (int mi = 0; mi < MI; mi++)
                ldsm_x4(af[mi][0], af[mi][1], af[mi][2], af[mi][3],
                        sa + ((abase[mi] + kg * 32) ^ lmask));
            uint32_t bf[NJ][2];
#pragma unroll
            for (int p = 0; p < NJ / 2; p++) {
                uint32_t r0, r1, r2, r3;
                ldsm_x4(r0, r1, r2, r3, sb + ((bbase[p] + kg * 32) ^ lmask));
                bf[2 * p][0] = r0; bf[2 * p + 1][0] = r1;
                bf[2 * p][1] = r2; bf[2 * p + 1][1] = r3;
            }
#pragma unroll
            for (int mi = 0; mi < MI; mi++)
#pragma unroll
                for (int nj = 0; nj < NJ; nj++) {
                    asm volatile(
                        "mma.sync.aligned.m16n8k8.row.col.f32.tf32.tf32.f32 "
                        "{%0,%1,%2,%3}, {%4,%5,%6,%7}, {%8,%9}, {%0,%1,%2,%3};\n"
                        : "+f"(acc[mi][nj][0]), "+f"(acc[mi][nj][1]),
                          "+f"(acc[mi][nj][2]), "+f"(acc[mi][nj][3])
                        : "r"(af[mi][0]), "r"(af[mi][1]), "r"(af[mi][2]), "r"(af[mi][3]),
                          "r"(bf[nj][0]), "r"(bf[nj][1]));
                }
        }

        if (t + GSTAGES - 1 < NK) issue(t + GSTAGES - 1);
        cp_commit();
        cp_wait<1>();
        __syncthreads();
    }

    // ---- epilogue ----
#pragma unroll
    for (int mi = 0; mi < MI; mi++) {
#pragma unroll
        for (int nj = 0; nj < NJ; nj++) {
            int m = m0 + wm * WT_M + mi * 16 + g;
            int n = n0 + wn * WT_N + nj * 8 + 2 * tig;
            if (n >= N) continue;
            float2 v0 = make_float2(acc[mi][nj][0], acc[mi][nj][1]);
            float2 v1 = make_float2(acc[mi][nj][2], acc[mi][nj][3]);
            if (EPI == EPI_SOFTPLUS) {
                float b0 = aux[n], b1 = aux[n + 1];
                v0.x += b0; v0.y += b1; v1.x += b0; v1.y += b1;
                v0.x = (v0.x > 20.f) ? v0.x : log1pf(__expf(v0.x));
                v0.y = (v0.y > 20.f) ? v0.y : log1pf(__expf(v0.y));
                v1.x = (v1.x > 20.f) ? v1.x : log1pf(__expf(v1.x));
                v1.y = (v1.y > 20.f) ? v1.y : log1pf(__expf(v1.y));
            } else if (EPI == EPI_RES) {
                float2 r0 = *reinterpret_cast<const float2*>(&aux[(size_t)m * ldc + n]);
                float2 r1 = *reinterpret_cast<const float2*>(&aux[(size_t)(m + 8) * ldc + n]);
                v0.x += r0.x; v0.y += r0.y; v1.x += r1.x; v1.y += r1.y;
            }
            *reinterpret_cast<float2*>(&C[(size_t)m * ldc + n]) = v0;
            *reinterpret_cast<float2*>(&C[(size_t)(m + 8) * ldc + n]) = v1;
        }
    }
}

// ---------------------------------------------------------------------------
// Reduce split-K partials -> g_xdbl (full) + g_xdbl_r (tf32-rounded)
// ---------------------------------------------------------------------------
__global__ __launch_bounds__(256)
void xdbl_reduce_kernel()
{
    const int i = blockIdx.x * 256 + threadIdx.x;
    const int n4 = MROWS * XDBLC / 4;
    if (i >= n4) return;
    const float4* p = reinterpret_cast<const float4*>(g_xpart);
    float4 a = p[i], b = p[i + n4], c = p[i + 2 * n4], d = p[i + 3 * n4];
    float4 r;
    r.x = (a.x + b.x) + (c.x + d.x);
    r.y = (a.y + b.y) + (c.y + d.y);
    r.z = (a.z + b.z) + (c.z + d.z);
    r.w = (a.w + b.w) + (c.w + d.w);
    reinterpret_cast<float4*>(g_xdbl)[i] = r;
    float4 rr;
    rr.x = rtf(r.x); rr.y = rtf(r.y); rr.z = rtf(r.z); rr.w = rtf(r.w);
    reinterpret_cast<float4*>(g_xdbl_r)[i] = rr;
}

// ---------------------------------------------------------------------------
// Depthwise causal conv (width 4) + SiLU; dual write (full + rounded)
// ---------------------------------------------------------------------------
__global__ __launch_bounds__(256)
void conv_silu_kernel(const float* __restrict__ conv_w,
                      const float* __restrict__ conv_b)
{
    int idx = blockIdx.x * 256 + threadIdx.x;
    if (idx >= MROWS * DINNER) return;
    int d = idx & (DINNER - 1);
    int m = idx >> 11;
    int l = m & (SEQ - 1);
    int brow = m - l;

    float s = conv_b[d];
#pragma unroll
    for (int j = 0; j < DCONV; j++) {
        int ll = l + j - (DCONV - 1);
        if (ll >= 0)
            s = fmaf(conv_w[d * DCONV + j],
                     g_xz[(size_t)(brow + ll) * XZCOLS + d], s);
    }
    float v = s * (1.f / (1.f + __expf(-s)));
    g_xc[idx]   = v;
    g_xc_r[idx] = rtf(v);
}

// ---------------------------------------------------------------------------
// SMEM-staged selective scan (16 channels x 16 states per block).
// y is tf32-rounded on store (it only feeds the out_proj GEMM).
// ---------------------------------------------------------------------------
#define TC 64
__global__ __launch_bounds__(256)
void scan_kernel(const float* __restrict__ A_log,
                 const float* __restrict__ Dvec)
{
    __shared__ __align__(16) float dt_s[TC][16];
    __shared__ __align__(16) float xc_s[TC][16];
    __shared__ __align__(16) float z_s [TC][16];
    __shared__ __align__(16) float B_s [TC][16];
    __shared__ __align__(16) float C_s [TC][16];
    __shared__ __align__(16) float y_s [TC][16];

    const int tid = threadIdx.x;
    const int s   = tid & 15;
    const int c   = tid >> 4;
    const int d0  = (blockIdx.x * 16) & (DINNER - 1);
    const int b   = (blockIdx.x * 16) >> 11;
    const int d   = d0 + c;

    const float As = -__expf(A_log[d * DSTATE + s]);
    const float Dd = Dvec[d];

    const int r = tid >> 2;
    const int q = tid & 3;
    const size_t mb = (size_t)b * SEQ;

    float4 p_dt, p_xc, p_z, p_B, p_C;
    auto ldg_chunk = [&](int t0) {
        size_t m = mb + t0 + r;
        p_dt = *reinterpret_cast<const float4*>(&g_dt [m * DINNER + d0 + q * 4]);
        p_xc = *reinterpret_cast<const float4*>(&g_xc [m * DINNER + d0 + q * 4]);
        p_z  = *reinterpret_cast<const float4*>(&g_xz [m * XZCOLS + DINNER + d0 + q * 4]);
        p_B  = *reinterpret_cast<const float4*>(&g_xdbl[m * XDBLC + DTRANK + q * 4]);
        p_C  = *reinterpret_cast<const float4*>(&g_xdbl[m * XDBLC + DTRANK + DSTATE + q * 4]);
    };
    auto sts_chunk = [&]() {
        *reinterpret_cast<float4*>(&dt_s[r][q * 4]) = p_dt;
        *reinterpret_cast<float4*>(&xc_s[r][q * 4]) = p_xc;
        *reinterpret_cast<float4*>(&z_s [r][q * 4]) = p_z;
        *reinterpret_cast<float4*>(&B_s [r][q * 4]) = p_B;
        *reinterpret_cast<float4*>(&C_s [r][q * 4]) = p_C;
    };

    ldg_chunk(0);
    sts_chunk();
    __syncthreads();

    float h = 0.f;
    for (int t0 = 0; t0 < SEQ; t0 += TC) {
        if (t0 + TC < SEQ) ldg_chunk(t0 + TC);

#pragma unroll 4
        for (int t = 0; t < TC; t++) {
            float dt_v = dt_s[t][c];
            float x_v  = xc_s[t][c];
            float Bv   = B_s [t][s];
            float Cv   = C_s [t][s];
            float dA = __expf(dt_v * As);
            h = fmaf(dA, h, dt_v * Bv * x_v);
            float p = h * Cv;
            p += __shfl_xor_sync(0xffffffffu, p, 1);
            p += __shfl_xor_sync(0xffffffffu, p, 2);
            p += __shfl_xor_sync(0xffffffffu, p, 4);
            p += __shfl_xor_sync(0xffffffffu, p, 8);
            if (s == 0) {
                float zv = z_s[t][c];
                float y  = fmaf(Dd, x_v, p);
                y *= zv * (1.f / (1.f + __expf(-zv)));
                y_s[t][c] = rtf(y);          // tf32-round for out_proj GEMM
            }
        }
        __syncthreads();

        {
            size_t m = mb + t0 + r;
            *reinterpret_cast<float4*>(&g_y[m * DINNER + d0 + q * 4]) =
                *reinterpret_cast<const float4*>(&y_s[r][q * 4]);
        }
        if (t0 + TC < SEQ) sts_chunk();
        __syncthreads();
    }
}

// ---------------------------------------------------------------------------
// LayerNorm over last dim (1024)
// ---------------------------------------------------------------------------
__global__ __launch_bounds__(256)
void ln_kernel(const float* __restrict__ h,
               const float* __restrict__ gamma,
               const float* __restrict__ beta,
               float* __restrict__ out)
{
    int m = blockIdx.x;
    const float* row = h + (size_t)m * DMODEL;
    float s = 0.f, s2 = 0.f;
    for (int i = threadIdx.x; i < DMODEL; i += 256) {
        float v = row[i];
        s += v;
        s2 = fmaf(v, v, s2);
    }
#pragma unroll
    for (int o = 16; o; o >>= 1) {
        s  += __shfl_xor_sync(0xffffffffu, s,  o);
        s2 += __shfl_xor_sync(0xffffffffu, s2, o);
    }
    __shared__ float ss[8], ss2[8];
    int w = threadIdx.x >> 5, ln = threadIdx.x & 31;
    if (ln == 0) { ss[w] = s; ss2[w] = s2; }
    __syncthreads();
    s = 0.f; s2 = 0.f;
#pragma unroll
    for (int i = 0; i < 8; i++) { s += ss[i]; s2 += ss2[i]; }
    float mu  = s * (1.f / DMODEL);
    float var = s2 * (1.f / DMODEL) - mu * mu;
    float inv = rsqrtf(var + 1e-5f);
    for (int i = threadIdx.x; i < DMODEL; i += 256) {
        float v = row[i];
        out[(size_t)m * DMODEL + i] = (v - mu) * inv * gamma[i] + beta[i];
    }
}

// ---------------------------------------------------------------------------
// Launch
// ---------------------------------------------------------------------------
extern "C" void kernel_launch(void* const* d_in, const int* in_sizes, int n_in,
                              void* d_out, int out_size)
{
    const float* x          = (const float*)d_in[0];
    const float* in_proj_w  = (const float*)d_in[1];
    const float* conv_w     = (const float*)d_in[2];
    const float* conv_b     = (const float*)d_in[3];
    const float* x_proj_w   = (const float*)d_in[4];
    const float* dt_proj_w  = (const float*)d_in[5];
    const float* dt_proj_b  = (const float*)d_in[6];
    const float* A_log      = (const float*)d_in[7];
    const float* Dvec       = (const float*)d_in[8];
    const float* out_proj_w = (const float*)d_in[9];
    const float* ln_gamma   = (const float*)d_in[10];
    const float* ln_beta    = (const float*)d_in[11];
    float* out = (float*)d_out;

    float *p_xz, *p_xcr, *p_xdblr, *p_xpart, *p_dt, *p_y, *p_h;
    float *p_xr, *p_winr, *p_woutr, *p_wxr, *p_wdtr;
    cudaGetSymbolAddress((void**)&p_xz,    g_xz);
    cudaGetSymbolAddress((void**)&p_xcr,   g_xc_r);
    cudaGetSymbolAddress((void**)&p_xdblr, g_xdbl_r);
    cudaGetSymbolAddress((void**)&p_xpart, g_xpart);
    cudaGetSymbolAddress((void**)&p_dt,    g_dt);
    cudaGetSymbolAddress((void**)&p_y,     g_y);
    cudaGetSymbolAddress((void**)&p_h,     g_h);
    cudaGetSymbolAddress((void**)&p_xr,    g_x_r);
    cudaGetSymbolAddress((void**)&p_winr,  g_win_r);
    cudaGetSymbolAddress((void**)&p_woutr, g_wout_r);
    cudaGetSymbolAddress((void**)&p_wxr,   g_wx_r);
    cudaGetSymbolAddress((void**)&p_wdtr,  g_wdt_r);

    const int SMEM256 = GSTAGES * (16384 + 32768);   // 144 KB
    const int SMEM128 = GSTAGES * (16384 + 16384);   //  96 KB
    cudaFuncSetAttribute(mma_gemm_nt<EPI_PLAIN, 256>,
                         cudaFuncAttributeMaxDynamicSharedMemorySize, SMEM256);
    cudaFuncSetAttribute(mma_gemm_nt<EPI_SOFTPLUS, 256>,
                         cudaFuncAttributeMaxDynamicSharedMemorySize, SMEM256);
    cudaFuncSetAttribute(mma_gemm_nt<EPI_RES, 256>,
                         cudaFuncAttributeMaxDynamicSharedMemorySize, SMEM256);
    cudaFuncSetAttribute(mma_gemm_nt<EPI_PLAIN, 128>,
                         cudaFuncAttributeMaxDynamicSharedMemorySize, SMEM128);

    // 0) tf32-round x and all weights
    round_tf32_kernel<<<(MROWS * DMODEL / 4 + 255) / 256, 256>>>(
        (const float4*)x, (float4*)p_xr, MROWS * DMODEL / 4);
    round_tf32_kernel<<<(XZCOLS * DMODEL / 4 + 255) / 256, 256>>>(
        (const float4*)in_proj_w, (float4*)p_winr, XZCOLS * DMODEL / 4);
    round_tf32_kernel<<<(DMODEL * DINNER / 4 + 255) / 256, 256>>>(
        (const float4*)out_proj_w, (float4*)p_woutr, DMODEL * DINNER / 4);
    round_tf32_kernel<<<(XDBLC * DINNER / 4 + 255) / 256, 256>>>(
        (const float4*)x_proj_w, (float4*)p_wxr, XDBLC * DINNER / 4);
    round_tf32_kernel<<<(DINNER * DTRANK / 4 + 255) / 256, 256>>>(
        (const float4*)dt_proj_w, (float4*)p_wdtr, DINNER * DTRANK / 4);

    // 1) in_proj: xz = x @ W_in^T   (4096 x 4096, K=1024)
    mma_gemm_nt<EPI_PLAIN, 256><<<dim3(XZCOLS / 256, MROWS / 128, 1), 256, SMEM256>>>(
        p_xr, DMODEL, p_winr, DMODEL, p_xz, XZCOLS,
        DMODEL, XZCOLS, nullptr, 0, 0);

    // 2) depthwise conv + silu -> xc (full + rounded)
    conv_silu_kernel<<<(MROWS * DINNER + 255) / 256, 256>>>(conv_w, conv_b);

    // 3) x_dbl partials: xc @ W_xproj^T  (4096 x 96, K=2048, split-K=4)
    mma_gemm_nt<EPI_PLAIN, 128><<<dim3(1, MROWS / 128, XSPLITK), 256, SMEM128>>>(
        p_xcr, DINNER, p_wxr, DINNER, p_xpart, XDBLC,
        DINNER / XSPLITK, XDBLC, nullptr,
        DINNER / XSPLITK, (size_t)MROWS * XDBLC);

    // 3b) reduce partials -> g_xdbl (+ rounded copy)
    xdbl_reduce_kernel<<<(MROWS * XDBLC / 4 + 255) / 256, 256>>>();

    // 4) dt = softplus(x_dbl[:, :64] @ W_dt^T + b)  (4096 x 2048, K=64)
    mma_gemm_nt<EPI_SOFTPLUS, 256><<<dim3(DINNER / 256, MROWS / 128, 1), 256, SMEM256>>>(
        p_xdblr, XDBLC, p_wdtr, DTRANK, p_dt, DINNER,
        DTRANK, DINNER, dt_proj_b, 0, 0);

    // 5) SMEM-staged selective scan (+ D-skip, * silu(z)) -> y (rounded)
    scan_kernel<<<(BATCH * DINNER) / 16, 256>>>(A_log, Dvec);

    // 6) out_proj + residual: h = y @ W_out^T + x   (4096 x 1024, K=2048)
    mma_gemm_nt<EPI_RES, 256><<<dim3(DMODEL / 256, MROWS / 128, 1), 256, SMEM256>>>(
        p_y, DINNER, p_woutr, DINNER, p_h, DMODEL,
        DINNER, DMODEL, x, 0, 0);

    // 7) LayerNorm -> out
    ln_kernel<<<MROWS, 256>>>(p_h, ln_gamma, ln_beta, out);
}

// round 8
// speedup vs baseline: 1.0355x; 1.0355x over previous
// R6 design, resubmission 2: 512-thread BN=256 tf32 GEMMs + pre-rounded operands.
#include <cuda_runtime.h>
#include <cuda_bf16.h>
#include <cstdint>

// ---------------------------------------------------------------------------
// Problem constants
// ---------------------------------------------------------------------------
#define BATCH   2
#define SEQ     2048
#define DMODEL  1024
#define DINNER  2048
#define DSTATE  16
#define DCONV   4
#define DTRANK  64
#define MROWS   (BATCH * SEQ)          // 4096
#define XZCOLS  (2 * DINNER)           // 4096
#define XDBLC   (DTRANK + 2 * DSTATE)  // 96
#define XSPLITK 8

// ---------------------------------------------------------------------------
// Scratch (device globals; no runtime allocation allowed)
// ---------------------------------------------------------------------------
__device__ float g_xz    [(size_t)MROWS * XZCOLS];   // [xi | z]
__device__ float g_xc_r  [(size_t)MROWS * DINNER];   // conv+silu, tf32-rounded
__device__ float g_xdbl  [(size_t)MROWS * XDBLC];    // [dt_r | B | C] full
__device__ float g_xdbl_r[(size_t)MROWS * XDBLC];    // tf32-rounded copy
__device__ float g_xpart [(size_t)XSPLITK * MROWS * XDBLC];
__device__ float g_dt    [(size_t)MROWS * DINNER];   // softplus(dt), full
__device__ float g_y     [(size_t)MROWS * DINNER];   // scan out (tf32-rounded)
__device__ float g_h     [(size_t)MROWS * DMODEL];   // out_proj + residual
// tf32-rounded inputs
__device__ float g_x_r   [(size_t)MROWS * DMODEL];
__device__ float g_win_r [(size_t)XZCOLS * DMODEL];
__device__ float g_wout_r[(size_t)DMODEL * DINNER];
__device__ float g_wx_r  [(size_t)XDBLC * DINNER];
__device__ float g_wdt_r [(size_t)DINNER * DTRANK];

enum { EPI_PLAIN = 0, EPI_SOFTPLUS = 1, EPI_RES = 2 };

// ---------------------------------------------------------------------------
// PTX helpers
// ---------------------------------------------------------------------------
__device__ __forceinline__ uint32_t f2tf32(float f) {
    uint32_t r;
    asm("cvt.rna.tf32.f32 %0, %1;" : "=r"(r) : "f"(f));
    return r;
}
__device__ __forceinline__ float rtf(float f) { return __uint_as_float(f2tf32(f)); }

__device__ __forceinline__ void cp_async16(uint32_t dst, const void* src) {
    asm volatile("cp.async.cg.shared.global [%0], [%1], 16;\n" :: "r"(dst), "l"(src));
}
__device__ __forceinline__ void cp_commit() {
    asm volatile("cp.async.commit_group;\n" ::: "memory");
}
template <int N> __device__ __forceinline__ void cp_wait() {
    asm volatile("cp.async.wait_group %0;\n" :: "n"(N) : "memory");
}
__device__ __forceinline__ void ldsm_x4(uint32_t& r0, uint32_t& r1,
                                        uint32_t& r2, uint32_t& r3, uint32_t addr) {
    asm volatile("ldmatrix.sync.aligned.m8n8.x4.shared.b16 {%0,%1,%2,%3}, [%4];\n"
                 : "=r"(r0), "=r"(r1), "=r"(r2), "=r"(r3) : "r"(addr));
}

// ---------------------------------------------------------------------------
// tf32 rounding copy kernel
// ---------------------------------------------------------------------------
__global__ __launch_bounds__(256)
void round_tf32_kernel(const float4* __restrict__ src, float4* __restrict__ dst, int n4)
{
    int i = blockIdx.x * 256 + threadIdx.x;
    if (i >= n4) return;
    float4 v = src[i];
    v.x = rtf(v.x); v.y = rtf(v.y); v.z = rtf(v.z); v.w = rtf(v.w);
    dst[i] = v;
}

// ---------------------------------------------------------------------------
// Tensor-core NT GEMM (tf32): C[M,N] = A[M,K]*B[N,K]^T, row-major.
// BM=128, BK=32, SW128 swizzle, cp.async 3-stage, ldmatrix.
// BN=256: 512 threads, 16 warps (4m x 4n), warp tile 32x64, 144 KB SMEM.
// BN=128: 256 threads,  8 warps (4m x 2n), warp tile 32x64,  96 KB SMEM.
// Inputs must already be tf32-rounded. blockIdx.z: k-slice.
// ---------------------------------------------------------------------------
#define GSTAGES 3

template <int EPI, int BN, int THREADS>
__global__ __launch_bounds__(THREADS)
void mma_gemm_nt(const float* __restrict__ A, int lda,
                 const float* __restrict__ B, int ldb,
                 float* __restrict__ C, int ldc,
                 int K, int N, const float* __restrict__ aux,
                 int kz, size_t cz)
{
    constexpr int NWARPS  = THREADS / 32;
    constexpr int NWARP_M = 4;
    constexpr int NWARP_N = NWARPS / NWARP_M;    // 4 (BN=256) or 2 (BN=128)
    constexpr int WT_M = 128 / NWARP_M;          // 32
    constexpr int WT_N = BN / NWARP_N;           // 64
    constexpr int MI = WT_M / 16;                // 2
    constexpr int NJ = WT_N / 8;                 // 8
    constexpr int A_BYTES = 128 * 32 * 4;        // 16 KB
    constexpr int B_BYTES = BN * 32 * 4;         // 16/32 KB
    constexpr int ACH = 128 * 8 / THREADS;       // A 16B-chunks per thread
    constexpr int BCH = BN * 8 / THREADS;        // B 16B-chunks per thread

    extern __shared__ __align__(16) char smem[];
    const uint32_t smem_u = (uint32_t)__cvta_generic_to_shared(smem);
    const uint32_t smA = smem_u;
    const uint32_t smB = smem_u + GSTAGES * A_BYTES;

    A += (size_t)blockIdx.z * kz;
    B += (size_t)blockIdx.z * kz;
    C += (size_t)blockIdx.z * cz;

    const int tid  = threadIdx.x;
    const int lane = tid & 31;
    const int wid  = tid >> 5;
    const int g    = lane >> 2;
    const int tig  = lane & 3;
    const int wm   = wid % NWARP_M;
    const int wn   = wid / NWARP_M;
    const int m0   = blockIdx.y * 128;
    const int n0   = blockIdx.x * BN;

    // --- cp.async source pointers / swizzled dst offsets ---
    const float* asrc[ACH];
    uint32_t aoff[ACH];
#pragma unroll
    for (int i = 0; i < ACH; i++) {
        int id = tid + i * THREADS;
        int r  = id >> 3;
        int ch = id & 7;
        aoff[i] = (uint32_t)((r * 128 + ch * 16) ^ ((r & 7) << 4));
        asrc[i] = A + (size_t)(m0 + r) * lda + ch * 4;
    }
    const float* bsrc[BCH];
    uint32_t boff[BCH];
#pragma unroll
    for (int i = 0; i < BCH; i++) {
        int id = tid + i * THREADS;
        int r  = id >> 3;
        int ch = id & 7;
        boff[i] = (uint32_t)((r * 128 + ch * 16) ^ ((r & 7) << 4));
        int br = n0 + r; if (br > N - 1) br = N - 1;
        bsrc[i] = B + (size_t)br * ldb + ch * 4;
    }

    // --- ldmatrix addressing ---
    const int lrow  = (lane & 7) + ((lane >> 3) & 1) * 8;
    const int lkb   = ((lane >> 4) & 1) * 16;
    const uint32_t lmask = (uint32_t)((lane & 7) << 4);
    uint32_t abase[MI], bbase[NJ / 2];
#pragma unroll
    for (int mi = 0; mi < MI; mi++)
        abase[mi] = (uint32_t)((wm * WT_M + mi * 16 + lrow) * 128 + lkb);
#pragma unroll
    for (int p = 0; p < NJ / 2; p++)
        bbase[p] = (uint32_t)((wn * WT_N + p * 16 + lrow) * 128 + lkb);

    float acc[MI][NJ][4];
#pragma unroll
    for (int mi = 0; mi < MI; mi++)
#pragma unroll
        for (int nj = 0; nj < NJ; nj++)
#pragma unroll
            for (int q = 0; q < 4; q++) acc[mi][nj][q] = 0.f;

    const int NK = K / 32;

    auto issue = [&](int t) {
        const int s = t % GSTAGES;
        const uint32_t sa = smA + s * A_BYTES;
        const uint32_t sb = smB + s * B_BYTES;
        const int k0 = t * 32;
#pragma unroll
        for (int i = 0; i < ACH; i++) cp_async16(sa + aoff[i], asrc[i] + k0);
#pragma unroll
        for (int i = 0; i < BCH; i++) cp_async16(sb + boff[i], bsrc[i] + k0);
    };

    issue(0); cp_commit();
    if (NK > 1) issue(1);
    cp_commit();
    cp_wait<1>();
    __syncthreads();

    for (int t = 0; t < NK; t++) {
        const int s = t % GSTAGES;
        const uint32_t sa = smA + s * A_BYTES;
        const uint32_t sb = smB + s * B_BYTES;

#pragma unroll
        for (int kg = 0; kg < 4; kg++) {
            uint32_t af[MI][4];
#pragma unroll
            for (int mi = 0; mi < MI; mi++)
                ldsm_x4(af[mi][0], af[mi][1], af[mi][2], af[mi][3],
                        sa + ((abase[mi] + kg * 32) ^ lmask));
            uint32_t bf[NJ][2];
#pragma unroll
            for (int p = 0; p < NJ / 2; p++) {
                uint32_t r0, r1, r2, r3;
                ldsm_x4(r0, r1, r2, r3, sb + ((bbase[p] + kg * 32) ^ lmask));
                bf[2 * p][0] = r0; bf[2 * p + 1][0] = r1;
                bf[2 * p][1] = r2; bf[2 * p + 1][1] = r3;
            }
#pragma unroll
            for (int mi = 0; mi < MI; mi++)
#pragma unroll
                for (int nj = 0; nj < NJ; nj++) {
                    asm volatile(
                        "mma.sync.aligned.m16n8k8.row.col.f32.tf32.tf32.f32 "
                        "{%0,%1,%2,%3}, {%4,%5,%6,%7}, {%8,%9}, {%0,%1,%2,%3};\n"
                        : "+f"(acc[mi][nj][0]), "+f"(acc[mi][nj][1]),
                          "+f"(acc[mi][nj][2]), "+f"(acc[mi][nj][3])
                        : "r"(af[mi][0]), "r"(af[mi][1]), "r"(af[mi][2]), "r"(af[mi][3]),
                          "r"(bf[nj][0]), "r"(bf[nj][1]));
                }
        }

        if (t + GSTAGES - 1 < NK) issue(t + GSTAGES - 1);
        cp_commit();
        cp_wait<1>();
        __syncthreads();
    }

    // ---- epilogue ----
#pragma unroll
    for (int mi = 0; mi < MI; mi++) {
#pragma unroll
        for (int nj = 0; nj < NJ; nj++) {
            int m = m0 + wm * WT_M + mi * 16 + g;
            int n = n0 + wn * WT_N + nj * 8 + 2 * tig;
            if (n >= N) continue;
            float2 v0 = make_float2(acc[mi][nj][0], acc[mi][nj][1]);
            float2 v1 = make_float2(acc[mi][nj][2], acc[mi][nj][3]);
            if (EPI == EPI_SOFTPLUS) {
                float b0 = aux[n], b1 = aux[n + 1];
                v0.x += b0; v0.y += b1; v1.x += b0; v1.y += b1;
                v0.x = (v0.x > 20.f) ? v0.x : log1pf(__expf(v0.x));
                v0.y = (v0.y > 20.f) ? v0.y : log1pf(__expf(v0.y));
                v1.x = (v1.x > 20.f) ? v1.x : log1pf(__expf(v1.x));
                v1.y = (v1.y > 20.f) ? v1.y : log1pf(__expf(v1.y));
            } else if (EPI == EPI_RES) {
                float2 r0 = *reinterpret_cast<const float2*>(&aux[(size_t)m * ldc + n]);
                float2 r1 = *reinterpret_cast<const float2*>(&aux[(size_t)(m + 8) * ldc + n]);
                v0.x += r0.x; v0.y += r0.y; v1.x += r1.x; v1.y += r1.y;
            }
            *reinterpret_cast<float2*>(&C[(size_t)m * ldc + n]) = v0;
            *reinterpret_cast<float2*>(&C[(size_t)(m + 8) * ldc + n]) = v1;
        }
    }
}

// ---------------------------------------------------------------------------
// Reduce split-K partials -> g_xdbl (full) + g_xdbl_r (tf32-rounded)
// ---------------------------------------------------------------------------
__global__ __launch_bounds__(256)
void xdbl_reduce_kernel()
{
    const int i = blockIdx.x * 256 + threadIdx.x;
    const int n4 = MROWS * XDBLC / 4;
    if (i >= n4) return;
    const float4* p = reinterpret_cast<const float4*>(g_xpart);
    float4 a0 = p[i];
    float4 a1 = p[i + n4];
    float4 a2 = p[i + 2 * n4];
    float4 a3 = p[i + 3 * n4];
    float4 a4 = p[i + 4 * n4];
    float4 a5 = p[i + 5 * n4];
    float4 a6 = p[i + 6 * n4];
    float4 a7 = p[i + 7 * n4];
    float4 r;
    r.x = ((a0.x + a1.x) + (a2.x + a3.x)) + ((a4.x + a5.x) + (a6.x + a7.x));
    r.y = ((a0.y + a1.y) + (a2.y + a3.y)) + ((a4.y + a5.y) + (a6.y + a7.y));
    r.z = ((a0.z + a1.z) + (a2.z + a3.z)) + ((a4.z + a5.z) + (a6.z + a7.z));
    r.w = ((a0.w + a1.w) + (a2.w + a3.w)) + ((a4.w + a5.w) + (a6.w + a7.w));
    reinterpret_cast<float4*>(g_xdbl)[i] = r;
    float4 rr;
    rr.x = rtf(r.x); rr.y = rtf(r.y); rr.z = rtf(r.z); rr.w = rtf(r.w);
    reinterpret_cast<float4*>(g_xdbl_r)[i] = rr;
}

// ---------------------------------------------------------------------------
// Depthwise causal conv (width 4) + SiLU -> g_xc_r (tf32-rounded)
// ---------------------------------------------------------------------------
__global__ __launch_bounds__(256)
void conv_silu_kernel(const float* __restrict__ conv_w,
                      const float* __restrict__ conv_b)
{
    int idx = blockIdx.x * 256 + threadIdx.x;
    if (idx >= MROWS * DINNER) return;
    int d = idx & (DINNER - 1);
    int m = idx >> 11;
    int l = m & (SEQ - 1);
    int brow = m - l;

    float s = conv_b[d];
#pragma unroll
    for (int j = 0; j < DCONV; j++) {
        int ll = l + j - (DCONV - 1);
        if (ll >= 0)
            s = fmaf(conv_w[d * DCONV + j],
                     g_xz[(size_t)(brow + ll) * XZCOLS + d], s);
    }
    float v = s * (1.f / (1.f + __expf(-s)));
    g_xc_r[idx] = rtf(v);
}

// ---------------------------------------------------------------------------
// SMEM-staged selective scan (16 channels x 16 states per block).
// ---------------------------------------------------------------------------
#define TC 64
__global__ __launch_bounds__(256)
void scan_kernel(const float* __restrict__ A_log,
                 const float* __restrict__ Dvec)
{
    __shared__ __align__(16) float dt_s[TC][16];
    __shared__ __align__(16) float xc_s[TC][16];
    __shared__ __align__(16) float z_s [TC][16];
    __shared__ __align__(16) float B_s [TC][16];
    __shared__ __align__(16) float C_s [TC][16];
    __shared__ __align__(16) float y_s [TC][16];

    const int tid = threadIdx.x;
    const int s   = tid & 15;
    const int c   = tid >> 4;
    const int d0  = (blockIdx.x * 16) & (DINNER - 1);
    const int b   = (blockIdx.x * 16) >> 11;
    const int d   = d0 + c;

    const float As = -__expf(A_log[d * DSTATE + s]);
    const float Dd = Dvec[d];

    const int r = tid >> 2;
    const int q = tid & 3;
    const size_t mb = (size_t)b * SEQ;

    float4 p_dt, p_xc, p_z, p_B, p_C;
    auto ldg_chunk = [&](int t0) {
        size_t m = mb + t0 + r;
        p_dt = *reinterpret_cast<const float4*>(&g_dt  [m * DINNER + d0 + q * 4]);
        p_xc = *reinterpret_cast<const float4*>(&g_xc_r[m * DINNER + d0 + q * 4]);
        p_z  = *reinterpret_cast<const float4*>(&g_xz  [m * XZCOLS + DINNER + d0 + q * 4]);
        p_B  = *reinterpret_cast<const float4*>(&g_xdbl[m * XDBLC + DTRANK + q * 4]);
        p_C  = *reinterpret_cast<const float4*>(&g_xdbl[m * XDBLC + DTRANK + DSTATE + q * 4]);
    };
    auto sts_chunk = [&]() {
        *reinterpret_cast<float4*>(&dt_s[r][q * 4]) = p_dt;
        *reinterpret_cast<float4*>(&xc_s[r][q * 4]) = p_xc;
        *reinterpret_cast<float4*>(&z_s [r][q * 4]) = p_z;
        *reinterpret_cast<float4*>(&B_s [r][q * 4]) = p_B;
        *reinterpret_cast<float4*>(&C_s [r][q * 4]) = p_C;
    };

    ldg_chunk(0);
    sts_chunk();
    __syncthreads();

    float h = 0.f;
    for (int t0 = 0; t0 < SEQ; t0 += TC) {
        if (t0 + TC < SEQ) ldg_chunk(t0 + TC);

#pragma unroll 4
        for (int t = 0; t < TC; t++) {
            float dt_v = dt_s[t][c];
            float x_v  = xc_s[t][c];
            float Bv   = B_s [t][s];
            float Cv   = C_s [t][s];
            float dA = __expf(dt_v * As);
            h = fmaf(dA, h, dt_v * Bv * x_v);
            float p = h * Cv;
            p += __shfl_xor_sync(0xffffffffu, p, 1);
            p += __shfl_xor_sync(0xffffffffu, p, 2);
            p += __shfl_xor_sync(0xffffffffu, p, 4);
            p += __shfl_xor_sync(0xffffffffu, p, 8);
            if (s == 0) {
                float zv = z_s[t][c];
                float y  = fmaf(Dd, x_v, p);
                y *= zv * (1.f / (1.f + __expf(-zv)));
                y_s[t][c] = rtf(y);
            }
        }
        __syncthreads();

        {
            size_t m = mb + t0 + r;
            *reinterpret_cast<float4*>(&g_y[m * DINNER + d0 + q * 4]) =
                *reinterpret_cast<const float4*>(&y_s[r][q * 4]);
        }
        if (t0 + TC < SEQ) sts_chunk();
        __syncthreads();
    }
}

// ---------------------------------------------------------------------------
// LayerNorm over last dim (1024)
// ---------------------------------------------------------------------------
__global__ __launch_bounds__(256)
void ln_kernel(const float* __restrict__ h,
               const float* __restrict__ gamma,
               const float* __restrict__ beta,
               float* __restrict__ out)
{
    int m = blockIdx.x;
    const float* row = h + (size_t)m * DMODEL;
    float s = 0.f, s2 = 0.f;
    for (int i = threadIdx.x; i < DMODEL; i += 256) {
        float v = row[i];
        s += v;
        s2 = fmaf(v, v, s2);
    }
#pragma unroll
    for (int o = 16; o; o >>= 1) {
        s  += __shfl_xor_sync(0xffffffffu, s,  o);
        s2 += __shfl_xor_sync(0xffffffffu, s2, o);
    }
    __shared__ float ss[8], ss2[8];
    int w = threadIdx.x >> 5, ln = threadIdx.x & 31;
    if (ln == 0) { ss[w] = s; ss2[w] = s2; }
    __syncthreads();
    s = 0.f; s2 = 0.f;
#pragma unroll
    for (int i = 0; i < 8; i++) { s += ss[i]; s2 += ss2[i]; }
    float mu  = s * (1.f / DMODEL);
    float var = s2 * (1.f / DMODEL) - mu * mu;
    float inv = rsqrtf(var + 1e-5f);
    for (int i = threadIdx.x; i < DMODEL; i += 256) {
        float v = row[i];
        out[(size_t)m * DMODEL + i] = (v - mu) * inv * gamma[i] + beta[i];
    }
}

// ---------------------------------------------------------------------------
// Launch
// ---------------------------------------------------------------------------
extern "C" void kernel_launch(void* const* d_in, const int* in_sizes, int n_in,
                              void* d_out, int out_size)
{
    const float* x          = (const float*)d_in[0];
    const float* in_proj_w  = (const float*)d_in[1];
    const float* conv_w     = (const float*)d_in[2];
    const float* conv_b     = (const float*)d_in[3];
    const float* x_proj_w   = (const float*)d_in[4];
    const float* dt_proj_w  = (const float*)d_in[5];
    const float* dt_proj_b  = (const float*)d_in[6];
    const float* A_log      = (const float*)d_in[7];
    const float* Dvec       = (const float*)d_in[8];
    const float* out_proj_w = (const float*)d_in[9];
    const float* ln_gamma   = (const float*)d_in[10];
    const float* ln_beta    = (const float*)d_in[11];
    float* out = (float*)d_out;

    float *p_xz, *p_xcr, *p_xdblr, *p_xpart, *p_dt, *p_y, *p_h;
    float *p_xr, *p_winr, *p_woutr, *p_wxr, *p_wdtr;
    cudaGetSymbolAddress((void**)&p_xz,    g_xz);
    cudaGetSymbolAddress((void**)&p_xcr,   g_xc_r);
    cudaGetSymbolAddress((void**)&p_xdblr, g_xdbl_r);
    cudaGetSymbolAddress((void**)&p_xpart, g_xpart);
    cudaGetSymbolAddress((void**)&p_dt,    g_dt);
    cudaGetSymbolAddress((void**)&p_y,     g_y);
    cudaGetSymbolAddress((void**)&p_h,     g_h);
    cudaGetSymbolAddress((void**)&p_xr,    g_x_r);
    cudaGetSymbolAddress((void**)&p_winr,  g_win_r);
    cudaGetSymbolAddress((void**)&p_woutr, g_wout_r);
    cudaGetSymbolAddress((void**)&p_wxr,   g_wx_r);
    cudaGetSymbolAddress((void**)&p_wdtr,  g_wdt_r);

    const int SMEM256 = GSTAGES * (16384 + 32768);   // 144 KB
    const int SMEM128 = GSTAGES * (16384 + 16384);   //  96 KB
    cudaFuncSetAttribute(mma_gemm_nt<EPI_PLAIN, 256, 512>,
                         cudaFuncAttributeMaxDynamicSharedMemorySize, SMEM256);
    cudaFuncSetAttribute(mma_gemm_nt<EPI_SOFTPLUS, 256, 512>,
                         cudaFuncAttributeMaxDynamicSharedMemorySize, SMEM256);
    cudaFuncSetAttribute(mma_gemm_nt<EPI_RES, 256, 512>,
                         cudaFuncAttributeMaxDynamicSharedMemorySize, SMEM256);
    cudaFuncSetAttribute(mma_gemm_nt<EPI_PLAIN, 128, 256>,
                         cudaFuncAttributeMaxDynamicSharedMemorySize, SMEM128);

    // 0) tf32-round x and all weights
    round_tf32_kernel<<<(MROWS * DMODEL / 4 + 255) / 256, 256>>>(
        (const float4*)x, (float4*)p_xr, MROWS * DMODEL / 4);
    round_tf32_kernel<<<(XZCOLS * DMODEL / 4 + 255) / 256, 256>>>(
        (const float4*)in_proj_w, (float4*)p_winr, XZCOLS * DMODEL / 4);
    round_tf32_kernel<<<(DMODEL * DINNER / 4 + 255) / 256, 256>>>(
        (const float4*)out_proj_w, (float4*)p_woutr, DMODEL * DINNER / 4);
    round_tf32_kernel<<<(XDBLC * DINNER / 4 + 255) / 256, 256>>>(
        (const float4*)x_proj_w, (float4*)p_wxr, XDBLC * DINNER / 4);
    round_tf32_kernel<<<(DINNER * DTRANK / 4 + 255) / 256, 256>>>(
        (const float4*)dt_proj_w, (float4*)p_wdtr, DINNER * DTRANK / 4);

    // 1) in_proj: xz = x @ W_in^T   (4096 x 4096, K=1024)
    mma_gemm_nt<EPI_PLAIN, 256, 512><<<dim3(XZCOLS / 256, MROWS / 128, 1), 512, SMEM256>>>(
        p_xr, DMODEL, p_winr, DMODEL, p_xz, XZCOLS,
        DMODEL, XZCOLS, nullptr, 0, 0);

    // 2) depthwise conv + silu -> xc (rounded)
    conv_silu_kernel<<<(MROWS * DINNER + 255) / 256, 256>>>(conv_w, conv_b);

    // 3) x_dbl partials: xc @ W_xproj^T  (4096 x 96, K=2048, split-K=8)
    mma_gemm_nt<EPI_PLAIN, 128, 256><<<dim3(1, MROWS / 128, XSPLITK), 256, SMEM128>>>(
        p_xcr, DINNER, p_wxr, DINNER, p_xpart, XDBLC,
        DINNER / XSPLITK, XDBLC, nullptr,
        DINNER / XSPLITK, (size_t)MROWS * XDBLC);

    // 3b) reduce partials -> g_xdbl (+ rounded copy)
    xdbl_reduce_kernel<<<(MROWS * XDBLC / 4 + 255) / 256, 256>>>();

    // 4) dt = softplus(x_dbl[:, :64] @ W_dt^T + b)  (4096 x 2048, K=64)
    mma_gemm_nt<EPI_SOFTPLUS, 256, 512><<<dim3(DINNER / 256, MROWS / 128, 1), 512, SMEM256>>>(
        p_xdblr, XDBLC, p_wdtr, DTRANK, p_dt, DINNER,
        DTRANK, DINNER, dt_proj_b, 0, 0);

    // 5) SMEM-staged selective scan (+ D-skip, * silu(z)) -> y (rounded)
    scan_kernel<<<(BATCH * DINNER) / 16, 256>>>(A_log, Dvec);

    // 6) out_proj + residual: h = y @ W_out^T + x   (4096 x 1024, K=2048)
    mma_gemm_nt<EPI_RES, 256, 512><<<dim3(DMODEL / 256, MROWS / 128, 1), 512, SMEM256>>>(
        p_y, DINNER, p_woutr, DINNER, p_h, DMODEL,
        DINNER, DMODEL, x, 0, 0);

    // 7) LayerNorm -> out
    ln_kernel<<<MROWS, 256>>>(p_h, ln_gamma, ln_beta, out);
}

// round 12
// speedup vs baseline: 1.2828x; 1.2388x over previous
// R10 design, resubmission 3: fp16 mma.sync (m16n8k16, f32 accum) GEMMs; rne pre-conversion.
#include <cuda_runtime.h>
#include <cuda_fp16.h>
#include <cstdint>

#define BATCH   2
#define SEQ     2048
#define DMODEL  1024
#define DINNER  2048
#define DSTATE  16
#define DCONV   4
#define DTRANK  64
#define MROWS   (BATCH * SEQ)          // 4096
#define XZCOLS  (2 * DINNER)           // 4096
#define XDBLC   (DTRANK + 2 * DSTATE)  // 96
#define XSPLITK 8

// ---------------------------------------------------------------------------
// Scratch (device globals)
// ---------------------------------------------------------------------------
__device__ float  g_xz    [(size_t)MROWS * XZCOLS];   // [xi | z] fp32
__device__ float  g_xc    [(size_t)MROWS * DINNER];   // conv+silu fp32 (scan)
__device__ __half g_xc_h  [(size_t)MROWS * DINNER];   // fp16 copy (x_proj A)
__device__ float  g_xdbl  [(size_t)MROWS * XDBLC];    // [dt_r | B | C] fp32 (scan)
__device__ __half g_xdbl_h[(size_t)MROWS * XDBLC];    // fp16 copy (dt A)
__device__ float  g_xpart [(size_t)XSPLITK * MROWS * XDBLC];
__device__ float  g_dt    [(size_t)MROWS * DINNER];   // softplus(dt) fp32 (scan)
__device__ __half g_y_h   [(size_t)MROWS * DINNER];   // scan out fp16 (out_proj A)
__device__ float  g_h     [(size_t)MROWS * DMODEL];   // out_proj + residual
// fp16 operands
__device__ __half g_x_h   [(size_t)MROWS * DMODEL];
__device__ __half g_win_h [(size_t)XZCOLS * DMODEL];
__device__ __half g_wout_h[(size_t)DMODEL * DINNER];
__device__ __half g_wx_h  [(size_t)XDBLC * DINNER];
__device__ __half g_wdt_h [(size_t)DINNER * DTRANK];

enum { EPI_PLAIN = 0, EPI_SOFTPLUS = 1, EPI_RES = 2 };

// ---------------------------------------------------------------------------
// PTX helpers
// ---------------------------------------------------------------------------
__device__ __forceinline__ void cp_async16(uint32_t dst, const void* src) {
    asm volatile("cp.async.cg.shared.global [%0], [%1], 16;\n" :: "r"(dst), "l"(src));
}
__device__ __forceinline__ void cp_commit() {
    asm volatile("cp.async.commit_group;\n" ::: "memory");
}
template <int N> __device__ __forceinline__ void cp_wait() {
    asm volatile("cp.async.wait_group %0;\n" :: "n"(N) : "memory");
}
__device__ __forceinline__ void ldsm_x4(uint32_t& r0, uint32_t& r1,
                                        uint32_t& r2, uint32_t& r3, uint32_t addr) {
    asm volatile("ldmatrix.sync.aligned.m8n8.x4.shared.b16 {%0,%1,%2,%3}, [%4];\n"
                 : "=r"(r0), "=r"(r1), "=r"(r2), "=r"(r3) : "r"(addr));
}
__device__ __forceinline__ uint32_t h2u(__half2 h) {
    return *reinterpret_cast<uint32_t*>(&h);
}

// ---------------------------------------------------------------------------
// fp32 -> fp16 (rne) conversion kernel: 4 floats -> 4 halves per thread
// ---------------------------------------------------------------------------
__global__ __launch_bounds__(256)
void cvt_half_kernel(const float4* __restrict__ src, uint2* __restrict__ dst, int n4)
{
    int i = blockIdx.x * 256 + threadIdx.x;
    if (i >= n4) return;
    float4 v = src[i];
    uint2 o;
    o.x = h2u(__floats2half2_rn(v.x, v.y));
    o.y = h2u(__floats2half2_rn(v.z, v.w));
    dst[i] = o;
}

// ---------------------------------------------------------------------------
// fp16 tensor-core NT GEMM: C[M,N] = A[M,K]*B[N,K]^T, fp32 accum/output.
// BM=128, BN=128, BK=64 (128B rows, SW128 XOR swizzle), 3-stage cp.async,
// ldmatrix.x4, mma.sync.m16n8k16. 256 threads = 8 warps (4m x 2n), warp
// tile 32x64. M%128==0, K%64==0; N may be <128 (B rows clamped, stores
// guarded). blockIdx.z: k-slice (A,B advance kz halves; C advances cz).
// ---------------------------------------------------------------------------
#define GSTAGES 3
template <int EPI>
__global__ __launch_bounds__(256)
void hmma_gemm_nt(const __half* __restrict__ A, int lda,
                  const __half* __restrict__ B, int ldb,
                  float* __restrict__ C, int ldc,
                  int K, int N, const float* __restrict__ aux,
                  int kz, size_t cz)
{
    constexpr int BK = 64;
    constexpr int T_BYTES = 128 * BK * 2;    // 16 KB per operand tile
    extern __shared__ __align__(16) char smem[];
    const uint32_t smem_u = (uint32_t)__cvta_generic_to_shared(smem);
    const uint32_t smA = smem_u;
    const uint32_t smB = smem_u + GSTAGES * T_BYTES;

    A += (size_t)blockIdx.z * kz;
    B += (size_t)blockIdx.z * kz;
    C += (size_t)blockIdx.z * cz;

    const int tid  = threadIdx.x, lane = tid & 31, wid = tid >> 5;
    const int g    = lane >> 2, tig = lane & 3;
    const int wm   = wid & 3, wn = wid >> 2;
    const int m0   = blockIdx.y * 128, n0 = blockIdx.x * 128;

    // cp.async: 128 rows x 128B (8 x 16B chunks) per operand, 4 chunks/thread
    const __half* asrc[4]; const __half* bsrc[4]; uint32_t soff[4];
#pragma unroll
    for (int i = 0; i < 4; i++) {
        int id = tid + i * 256, r = id >> 3, ch = id & 7;
        soff[i] = (uint32_t)((r * 128 + ch * 16) ^ ((r & 7) << 4));
        asrc[i] = A + (size_t)(m0 + r) * lda + ch * 8;
        int br = n0 + r; if (br > N - 1) br = N - 1;
        bsrc[i] = B + (size_t)br * ldb + ch * 8;
    }

    // ldmatrix addressing (k16 = 32B per kg step)
    const int lrow  = (lane & 7) + ((lane >> 3) & 1) * 8;
    const int lkb   = ((lane >> 4) & 1) * 16;
    const uint32_t lmask = (uint32_t)((lane & 7) << 4);
    uint32_t abase[2], bbase[4];
#pragma unroll
    for (int mi = 0; mi < 2; mi++)
        abase[mi] = (uint32_t)((wm * 32 + mi * 16 + lrow) * 128 + lkb);
#pragma unroll
    for (int p = 0; p < 4; p++)
        bbase[p] = (uint32_t)((wn * 64 + p * 16 + lrow) * 128 + lkb);

    float acc[2][8][4];
#pragma unroll
    for (int mi = 0; mi < 2; mi++)
#pragma unroll
        for (int nj = 0; nj < 8; nj++)
#pragma unroll
            for (int q = 0; q < 4; q++) acc[mi][nj][q] = 0.f;

    const int NK = K / BK;
    auto issue = [&](int t) {
        const int s = t % GSTAGES;
        const uint32_t sa = smA + s * T_BYTES;
        const uint32_t sB = smB + s * T_BYTES;
        const int k0 = t * BK;
#pragma unroll
        for (int i = 0; i < 4; i++) {
            cp_async16(sa + soff[i], asrc[i] + k0);
            cp_async16(sB + soff[i], bsrc[i] + k0);
        }
    };

    issue(0); cp_commit();
    if (NK > 1) issue(1);
    cp_commit();

    for (int t = 0; t < NK; t++) {
        if (t + 1 < NK) cp_wait<1>(); else cp_wait<0>();
        __syncthreads();
        const int s = t % GSTAGES;
        const uint32_t sa = smA + s * T_BYTES;
        const uint32_t sB = smB + s * T_BYTES;

#pragma unroll
        for (int kg = 0; kg < 4; kg++) {       // 4 x k16 groups per BK=64
            uint32_t af[2][4];
#pragma unroll
            for (int mi = 0; mi < 2; mi++)
                ldsm_x4(af[mi][0], af[mi][1], af[mi][2], af[mi][3],
                        sa + ((abase[mi] + kg * 32) ^ lmask));
            uint32_t bf[8][2];
#pragma unroll
            for (int p = 0; p < 4; p++) {
                uint32_t r0, r1, r2, r3;
                ldsm_x4(r0, r1, r2, r3, sB + ((bbase[p] + kg * 32) ^ lmask));
                bf[2 * p][0] = r0; bf[2 * p + 1][0] = r1;
                bf[2 * p][1] = r2; bf[2 * p + 1][1] = r3;
            }
#pragma unroll
            for (int mi = 0; mi < 2; mi++)
#pragma unroll
                for (int nj = 0; nj < 8; nj++) {
                    asm volatile(
                        "mma.sync.aligned.m16n8k16.row.col.f32.f16.f16.f32 "
                        "{%0,%1,%2,%3}, {%4,%5,%6,%7}, {%8,%9}, {%0,%1,%2,%3};\n"
                        : "+f"(acc[mi][nj][0]), "+f"(acc[mi][nj][1]),
                          "+f"(acc[mi][nj][2]), "+f"(acc[mi][nj][3])
                        : "r"(af[mi][0]), "r"(af[mi][1]), "r"(af[mi][2]), "r"(af[mi][3]),
                          "r"(bf[nj][0]), "r"(bf[nj][1]));
                }
        }
        if (t + 2 < NK) issue(t + 2);
        cp_commit();
    }

    // ---- epilogue ----
#pragma unroll
    for (int mi = 0; mi < 2; mi++) {
#pragma unroll
        for (int nj = 0; nj < 8; nj++) {
            int m = m0 + wm * 32 + mi * 16 + g;
            int n = n0 + wn * 64 + nj * 8 + 2 * tig;
            if (n >= N) continue;
            float2 v0 = make_float2(acc[mi][nj][0], acc[mi][nj][1]);
            float2 v1 = make_float2(acc[mi][nj][2], acc[mi][nj][3]);
            if (EPI == EPI_SOFTPLUS) {
                float b0 = aux[n], b1 = aux[n + 1];
                v0.x += b0; v0.y += b1; v1.x += b0; v1.y += b1;
                v0.x = (v0.x > 20.f) ? v0.x : log1pf(__expf(v0.x));
                v0.y = (v0.y > 20.f) ? v0.y : log1pf(__expf(v0.y));
                v1.x = (v1.x > 20.f) ? v1.x : log1pf(__expf(v1.x));
                v1.y = (v1.y > 20.f) ? v1.y : log1pf(__expf(v1.y));
            } else if (EPI == EPI_RES) {
                float2 r0 = *reinterpret_cast<const float2*>(&aux[(size_t)m * ldc + n]);
                float2 r1 = *reinterpret_cast<const float2*>(&aux[(size_t)(m + 8) * ldc + n]);
                v0.x += r0.x; v0.y += r0.y; v1.x += r1.x; v1.y += r1.y;
            }
            *reinterpret_cast<float2*>(&C[(size_t)m * ldc + n]) = v0;
            *reinterpret_cast<float2*>(&C[(size_t)(m + 8) * ldc + n]) = v1;
        }
    }
}

// ---------------------------------------------------------------------------
// Split-K reduce -> g_xdbl (fp32, for scan) + g_xdbl_h (fp16, for dt GEMM)
// ---------------------------------------------------------------------------
__global__ __launch_bounds__(256)
void xdbl_reduce_kernel()
{
    const int i = blockIdx.x * 256 + threadIdx.x;
    const int n4 = MROWS * XDBLC / 4;
    if (i >= n4) return;
    const float4* p = reinterpret_cast<const float4*>(g_xpart);
    float4 a0 = p[i],          a1 = p[i + n4],     a2 = p[i + 2 * n4], a3 = p[i + 3 * n4];
    float4 a4 = p[i + 4 * n4], a5 = p[i + 5 * n4], a6 = p[i + 6 * n4], a7 = p[i + 7 * n4];
    float4 r;
    r.x = ((a0.x + a1.x) + (a2.x + a3.x)) + ((a4.x + a5.x) + (a6.x + a7.x));
    r.y = ((a0.y + a1.y) + (a2.y + a3.y)) + ((a4.y + a5.y) + (a6.y + a7.y));
    r.z = ((a0.z + a1.z) + (a2.z + a3.z)) + ((a4.z + a5.z) + (a6.z + a7.z));
    r.w = ((a0.w + a1.w) + (a2.w + a3.w)) + ((a4.w + a5.w) + (a6.w + a7.w));
    reinterpret_cast<float4*>(g_xdbl)[i] = r;
    uint2 o;
    o.x = h2u(__floats2half2_rn(r.x, r.y));
    o.y = h2u(__floats2half2_rn(r.z, r.w));
    reinterpret_cast<uint2*>(g_xdbl_h)[i] = o;
}

// ---------------------------------------------------------------------------
// Depthwise causal conv (width 4) + SiLU -> g_xc (fp32) + g_xc_h (fp16)
// ---------------------------------------------------------------------------
__global__ __launch_bounds__(256)
void conv_silu_kernel(const float* __restrict__ conv_w,
                      const float* __restrict__ conv_b)
{
    int idx = blockIdx.x * 256 + threadIdx.x;
    if (idx >= MROWS * DINNER) return;
    int d = idx & (DINNER - 1);
    int m = idx >> 11;
    int l = m & (SEQ - 1);
    int brow = m - l;
    float s = conv_b[d];
#pragma unroll
    for (int j = 0; j < DCONV; j++) {
        int ll = l + j - (DCONV - 1);
        if (ll >= 0)
            s = fmaf(conv_w[d * DCONV + j], g_xz[(size_t)(brow + ll) * XZCOLS + d], s);
    }
    float v = s * (1.f / (1.f + __expf(-s)));
    g_xc[idx]   = v;
    g_xc_h[idx] = __float2half_rn(v);
}

// ---------------------------------------------------------------------------
// SMEM-staged selective scan; y written directly as fp16 for out_proj
// ---------------------------------------------------------------------------
#define TC 64
__global__ __launch_bounds__(256)
void scan_kernel(const float* __restrict__ A_log,
                 const float* __restrict__ Dvec)
{
    __shared__ __align__(16) float dt_s[TC][16];
    __shared__ __align__(16) float xc_s[TC][16];
    __shared__ __align__(16) float z_s [TC][16];
    __shared__ __align__(16) float B_s [TC][16];
    __shared__ __align__(16) float C_s [TC][16];
    __shared__ __align__(16) float y_s [TC][16];

    const int tid = threadIdx.x;
    const int s   = tid & 15;
    const int c   = tid >> 4;
    const int d0  = (blockIdx.x * 16) & (DINNER - 1);
    const int b   = (blockIdx.x * 16) >> 11;
    const int d   = d0 + c;

    const float As = -__expf(A_log[d * DSTATE + s]);
    const float Dd = Dvec[d];

    const int r = tid >> 2, q = tid & 3;
    const size_t mb = (size_t)b * SEQ;

    float4 p_dt, p_xc, p_z, p_B, p_C;
    auto ldg_chunk = [&](int t0) {
        size_t m = mb + t0 + r;
        p_dt = *reinterpret_cast<const float4*>(&g_dt  [m * DINNER + d0 + q * 4]);
        p_xc = *reinterpret_cast<const float4*>(&g_xc  [m * DINNER + d0 + q * 4]);
        p_z  = *reinterpret_cast<const float4*>(&g_xz  [m * XZCOLS + DINNER + d0 + q * 4]);
        p_B  = *reinterpret_cast<const float4*>(&g_xdbl[m * XDBLC + DTRANK + q * 4]);
        p_C  = *reinterpret_cast<const float4*>(&g_xdbl[m * XDBLC + DTRANK + DSTATE + q * 4]);
    };
    auto sts_chunk = [&]() {
        *reinterpret_cast<float4*>(&dt_s[r][q * 4]) = p_dt;
        *reinterpret_cast<float4*>(&xc_s[r][q * 4]) = p_xc;
        *reinterpret_cast<float4*>(&z_s [r][q * 4]) = p_z;
        *reinterpret_cast<float4*>(&B_s [r][q * 4]) = p_B;
        *reinterpret_cast<float4*>(&C_s [r][q * 4]) = p_C;
    };

    ldg_chunk(0);
    sts_chunk();
    __syncthreads();

    float h = 0.f;
    for (int t0 = 0; t0 < SEQ; t0 += TC) {
        if (t0 + TC < SEQ) ldg_chunk(t0 + TC);
#pragma unroll 4
        for (int t = 0; t < TC; t++) {
            float dt_v = dt_s[t][c];
            float x_v  = xc_s[t][c];
            float Bv   = B_s [t][s];
            float Cv   = C_s [t][s];
            float dA = __expf(dt_v * As);
            h = fmaf(dA, h, dt_v * Bv * x_v);
            float p = h * Cv;
            p += __shfl_xor_sync(0xffffffffu, p, 1);
            p += __shfl_xor_sync(0xffffffffu, p, 2);
            p += __shfl_xor_sync(0xffffffffu, p, 4);
            p += __shfl_xor_sync(0xffffffffu, p, 8);
            if (s == 0) {
                float zv = z_s[t][c];
                float y  = fmaf(Dd, x_v, p);
                y *= zv * (1.f / (1.f + __expf(-zv)));
                y_s[t][c] = y;
            }
        }
        __syncthreads();
        {
            size_t m = mb + t0 + r;
            float4 yv = *reinterpret_cast<const float4*>(&y_s[r][q * 4]);
            uint2 o;
            o.x = h2u(__floats2half2_rn(yv.x, yv.y));
            o.y = h2u(__floats2half2_rn(yv.z, yv.w));
            *reinterpret_cast<uint2*>(&g_y_h[m * DINNER + d0 + q * 4]) = o;
        }
        if (t0 + TC < SEQ) sts_chunk();
        __syncthreads();
    }
}

// ---------------------------------------------------------------------------
// LayerNorm
// ---------------------------------------------------------------------------
__global__ __launch_bounds__(256)
void ln_kernel(const float* __restrict__ h,
               const float* __restrict__ gamma,
               const float* __restrict__ beta,
               float* __restrict__ out)
{
    int m = blockIdx.x;
    const float* row = h + (size_t)m * DMODEL;
    float s = 0.f, s2 = 0.f;
    for (int i = threadIdx.x; i < DMODEL; i += 256) {
        float v = row[i];
        s += v;
        s2 = fmaf(v, v, s2);
    }
#pragma unroll
    for (int o = 16; o; o >>= 1) {
        s  += __shfl_xor_sync(0xffffffffu, s,  o);
        s2 += __shfl_xor_sync(0xffffffffu, s2, o);
    }
    __shared__ float ss[8], ss2[8];
    int w = threadIdx.x >> 5, ln = threadIdx.x & 31;
    if (ln == 0) { ss[w] = s; ss2[w] = s2; }
    __syncthreads();
    s = 0.f; s2 = 0.f;
#pragma unroll
    for (int i = 0; i < 8; i++) { s += ss[i]; s2 += ss2[i]; }
    float mu  = s * (1.f / DMODEL);
    float var = s2 * (1.f / DMODEL) - mu * mu;
    float inv = rsqrtf(var + 1e-5f);
    for (int i = threadIdx.x; i < DMODEL; i += 256) {
        float v = row[i];
        out[(size_t)m * DMODEL + i] = (v - mu) * inv * gamma[i] + beta[i];
    }
}

// ---------------------------------------------------------------------------
// Launch
// ---------------------------------------------------------------------------
extern "C" void kernel_launch(void* const* d_in, const int* in_sizes, int n_in,
                              void* d_out, int out_size)
{
    const float* x          = (const float*)d_in[0];
    const float* in_proj_w  = (const float*)d_in[1];
    const float* conv_w     = (const float*)d_in[2];
    const float* conv_b     = (const float*)d_in[3];
    const float* x_proj_w   = (const float*)d_in[4];
    const float* dt_proj_w  = (const float*)d_in[5];
    const float* dt_proj_b  = (const float*)d_in[6];
    const float* A_log      = (const float*)d_in[7];
    const float* Dvec       = (const float*)d_in[8];
    const float* out_proj_w = (const float*)d_in[9];
    const float* ln_gamma   = (const float*)d_in[10];
    const float* ln_beta    = (const float*)d_in[11];
    float* out = (float*)d_out;

    float  *p_xz, *p_xpart, *p_dt, *p_h;
    __half *p_xch, *p_xdblh, *p_yh, *p_xh, *p_winh, *p_wouth, *p_wxh, *p_wdth;
    cudaGetSymbolAddress((void**)&p_xz,    g_xz);
    cudaGetSymbolAddress((void**)&p_xch,   g_xc_h);
    cudaGetSymbolAddress((void**)&p_xdblh, g_xdbl_h);
    cudaGetSymbolAddress((void**)&p_xpart, g_xpart);
    cudaGetSymbolAddress((void**)&p_dt,    g_dt);
    cudaGetSymbolAddress((void**)&p_yh,    g_y_h);
    cudaGetSymbolAddress((void**)&p_h,     g_h);
    cudaGetSymbolAddress((void**)&p_xh,    g_x_h);
    cudaGetSymbolAddress((void**)&p_winh,  g_win_h);
    cudaGetSymbolAddress((void**)&p_wouth, g_wout_h);
    cudaGetSymbolAddress((void**)&p_wxh,   g_wx_h);
    cudaGetSymbolAddress((void**)&p_wdth,  g_wdt_h);

    const int SMEM = GSTAGES * (16384 + 16384);   // 96 KB
    cudaFuncSetAttribute(hmma_gemm_nt<EPI_PLAIN>,
                         cudaFuncAttributeMaxDynamicSharedMemorySize, SMEM);
    cudaFuncSetAttribute(hmma_gemm_nt<EPI_SOFTPLUS>,
                         cudaFuncAttributeMaxDynamicSharedMemorySize, SMEM);
    cudaFuncSetAttribute(hmma_gemm_nt<EPI_RES>,
                         cudaFuncAttributeMaxDynamicSharedMemorySize, SMEM);

    // 1-3) fp16 conversions needed by in_proj (in_proj lands 4th = ncu slot)
    cvt_half_kernel<<<MROWS * DMODEL / 4 / 256, 256>>>(
        (const float4*)x, (uint2*)p_xh, MROWS * DMODEL / 4);
    cvt_half_kernel<<<XZCOLS * DMODEL / 4 / 256, 256>>>(
        (const float4*)in_proj_w, (uint2*)p_winh, XZCOLS * DMODEL / 4);
    cvt_half_kernel<<<DMODEL * DINNER / 4 / 256, 256>>>(
        (const float4*)out_proj_w, (uint2*)p_wouth, DMODEL * DINNER / 4);

    // 4) in_proj: xz = x @ W_in^T   (4096 x 4096, K=1024)
    hmma_gemm_nt<EPI_PLAIN><<<dim3(XZCOLS / 128, MROWS / 128, 1), 256, SMEM>>>(
        p_xh, DMODEL, p_winh, DMODEL, p_xz, XZCOLS,
        DMODEL, XZCOLS, nullptr, 0, 0);

    // 5-6) remaining weight conversions
    cvt_half_kernel<<<XDBLC * DINNER / 4 / 256, 256>>>(
        (const float4*)x_proj_w, (uint2*)p_wxh, XDBLC * DINNER / 4);
    cvt_half_kernel<<<DINNER * DTRANK / 4 / 256, 256>>>(
        (const float4*)dt_proj_w, (uint2*)p_wdth, DINNER * DTRANK / 4);

    // 7) conv + silu -> g_xc (fp32) + g_xc_h (fp16)
    conv_silu_kernel<<<(MROWS * DINNER + 255) / 256, 256>>>(conv_w, conv_b);

    // 8) x_proj (split-K=8): xc @ W_x^T  (4096 x 96, K=2048)
    hmma_gemm_nt<EPI_PLAIN><<<dim3(1, MROWS / 128, XSPLITK), 256, SMEM>>>(
        p_xch, DINNER, p_wxh, DINNER, p_xpart, XDBLC,
        DINNER / XSPLITK, XDBLC, nullptr,
        DINNER / XSPLITK, (size_t)MROWS * XDBLC);

    // 9) reduce partials -> g_xdbl (+ fp16 copy)
    xdbl_reduce_kernel<<<(MROWS * XDBLC / 4 + 255) / 256, 256>>>();

    // 10) dt = softplus(x_dbl[:, :64] @ W_dt^T + b)  (4096 x 2048, K=64)
    hmma_gemm_nt<EPI_SOFTPLUS><<<dim3(DINNER / 128, MROWS / 128, 1), 256, SMEM>>>(
        p_xdblh, XDBLC, p_wdth, DTRANK, p_dt, DINNER,
        DTRANK, DINNER, dt_proj_b, 0, 0);

    // 11) selective scan (+ D-skip, * silu(z)) -> g_y_h
    scan_kernel<<<(BATCH * DINNER) / 16, 256>>>(A_log, Dvec);

    // 12) out_proj + residual: h = y @ W_out^T + x   (4096 x 1024, K=2048)
    hmma_gemm_nt<EPI_RES><<<dim3(DMODEL / 128, MROWS / 128, 1), 256, SMEM>>>(
        p_yh, DINNER, p_wouth, DINNER, p_h, DMODEL,
        DINNER, DMODEL, x, 0, 0);

    // 13) LayerNorm -> out
    ln_kernel<<<MROWS, 256>>>(p_h, ln_gamma, ln_beta, out);
}

// round 14
// speedup vs baseline: 1.3537x; 1.0553x over previous
// R13: 2 CTAs/SM on fp16 GEMMs (launch_bounds 256,2) + fp16-only xc stream.
#include <cuda_runtime.h>
#include <cuda_fp16.h>
#include <cstdint>

#define BATCH   2
#define SEQ     2048
#define DMODEL  1024
#define DINNER  2048
#define DSTATE  16
#define DCONV   4
#define DTRANK  64
#define MROWS   (BATCH * SEQ)          // 4096
#define XZCOLS  (2 * DINNER)           // 4096
#define XDBLC   (DTRANK + 2 * DSTATE)  // 96
#define XSPLITK 8

// ---------------------------------------------------------------------------
// Scratch (device globals)
// ---------------------------------------------------------------------------
__device__ float  g_xz    [(size_t)MROWS * XZCOLS];   // [xi | z] fp32
__device__ __half g_xc_h  [(size_t)MROWS * DINNER];   // conv+silu fp16 (scan + x_proj A)
__device__ float  g_xdbl  [(size_t)MROWS * XDBLC];    // [dt_r | B | C] fp32 (scan)
__device__ __half g_xdbl_h[(size_t)MROWS * XDBLC];    // fp16 copy (dt A)
__device__ float  g_xpart [(size_t)XSPLITK * MROWS * XDBLC];
__device__ float  g_dt    [(size_t)MROWS * DINNER];   // softplus(dt) fp32 (scan)
__device__ __half g_y_h   [(size_t)MROWS * DINNER];   // scan out fp16 (out_proj A)
__device__ float  g_h     [(size_t)MROWS * DMODEL];   // out_proj + residual
// fp16 operands
__device__ __half g_x_h   [(size_t)MROWS * DMODEL];
__device__ __half g_win_h [(size_t)XZCOLS * DMODEL];
__device__ __half g_wout_h[(size_t)DMODEL * DINNER];
__device__ __half g_wx_h  [(size_t)XDBLC * DINNER];
__device__ __half g_wdt_h [(size_t)DINNER * DTRANK];

enum { EPI_PLAIN = 0, EPI_SOFTPLUS = 1, EPI_RES = 2 };

// ---------------------------------------------------------------------------
// PTX helpers
// ---------------------------------------------------------------------------
__device__ __forceinline__ void cp_async16(uint32_t dst, const void* src) {
    asm volatile("cp.async.cg.shared.global [%0], [%1], 16;\n" :: "r"(dst), "l"(src));
}
__device__ __forceinline__ void cp_commit() {
    asm volatile("cp.async.commit_group;\n" ::: "memory");
}
template <int N> __device__ __forceinline__ void cp_wait() {
    asm volatile("cp.async.wait_group %0;\n" :: "n"(N) : "memory");
}
__device__ __forceinline__ void ldsm_x4(uint32_t& r0, uint32_t& r1,
                                        uint32_t& r2, uint32_t& r3, uint32_t addr) {
    asm volatile("ldmatrix.sync.aligned.m8n8.x4.shared.b16 {%0,%1,%2,%3}, [%4];\n"
                 : "=r"(r0), "=r"(r1), "=r"(r2), "=r"(r3) : "r"(addr));
}
__device__ __forceinline__ uint32_t h2u(__half2 h) {
    return *reinterpret_cast<uint32_t*>(&h);
}

// ---------------------------------------------------------------------------
// fp32 -> fp16 (rne) conversion kernel
// ---------------------------------------------------------------------------
__global__ __launch_bounds__(256)
void cvt_half_kernel(const float4* __restrict__ src, uint2* __restrict__ dst, int n4)
{
    int i = blockIdx.x * 256 + threadIdx.x;
    if (i >= n4) return;
    float4 v = src[i];
    uint2 o;
    o.x = h2u(__floats2half2_rn(v.x, v.y));
    o.y = h2u(__floats2half2_rn(v.z, v.w));
    dst[i] = o;
}

// ---------------------------------------------------------------------------
// fp16 tensor-core NT GEMM: C[M,N] = A[M,K]*B[N,K]^T, fp32 accum/output.
// BM=128, BN=128, BK=64 (128B rows, SW128 XOR swizzle), 3-stage cp.async,
// ldmatrix.x4, mma.sync.m16n8k16. 256 threads = 8 warps (4m x 2n), warp
// tile 32x64. launch_bounds(256,2): <=128 regs so 2 CTAs/SM co-reside
// (2 x 96KB = 192KB < 227KB). M%128==0, K%64==0; N<128 handled.
// ---------------------------------------------------------------------------
#define GSTAGES 3
template <int EPI>
__global__ __launch_bounds__(256, 2)
void hmma_gemm_nt(const __half* __restrict__ A, int lda,
                  const __half* __restrict__ B, int ldb,
                  float* __restrict__ C, int ldc,
                  int K, int N, const float* __restrict__ aux,
                  int kz, size_t cz)
{
    constexpr int BK = 64;
    constexpr int T_BYTES = 128 * BK * 2;    // 16 KB per operand tile
    extern __shared__ __align__(16) char smem[];
    const uint32_t smem_u = (uint32_t)__cvta_generic_to_shared(smem);
    const uint32_t smA = smem_u;
    const uint32_t smB = smem_u + GSTAGES * T_BYTES;

    A += (size_t)blockIdx.z * kz;
    B += (size_t)blockIdx.z * kz;
    C += (size_t)blockIdx.z * cz;

    const int tid  = threadIdx.x, lane = tid & 31, wid = tid >> 5;
    const int g    = lane >> 2, tig = lane & 3;
    const int wm   = wid & 3, wn = wid >> 2;
    const int m0   = blockIdx.y * 128, n0 = blockIdx.x * 128;

    // cp.async: 128 rows x 128B (8 x 16B chunks) per operand, 4 chunks/thread
    const __half* asrc[4]; const __half* bsrc[4]; uint32_t soff[4];
#pragma unroll
    for (int i = 0; i < 4; i++) {
        int id = tid + i * 256, r = id >> 3, ch = id & 7;
        soff[i] = (uint32_t)((r * 128 + ch * 16) ^ ((r & 7) << 4));
        asrc[i] = A + (size_t)(m0 + r) * lda + ch * 8;
        int br = n0 + r; if (br > N - 1) br = N - 1;
        bsrc[i] = B + (size_t)br * ldb + ch * 8;
    }

    // ldmatrix addressing (k16 = 32B per kg step)
    const int lrow  = (lane & 7) + ((lane >> 3) & 1) * 8;
    const int lkb   = ((lane >> 4) & 1) * 16;
    const uint32_t lmask = (uint32_t)((lane & 7) << 4);
    uint32_t abase[2], bbase[4];
#pragma unroll
    for (int mi = 0; mi < 2; mi++)
        abase[mi] = (uint32_t)((wm * 32 + mi * 16 + lrow) * 128 + lkb);
#pragma unroll
    for (int p = 0; p < 4; p++)
        bbase[p] = (uint32_t)((wn * 64 + p * 16 + lrow) * 128 + lkb);

    float acc[2][8][4];
#pragma unroll
    for (int mi = 0; mi < 2; mi++)
#pragma unroll
        for (int nj = 0; nj < 8; nj++)
#pragma unroll
            for (int q = 0; q < 4; q++) acc[mi][nj][q] = 0.f;

    const int NK = K / BK;
    auto issue = [&](int t) {
        const int s = t % GSTAGES;
        const uint32_t sa = smA + s * T_BYTES;
        const uint32_t sB = smB + s * T_BYTES;
        const int k0 = t * BK;
#pragma unroll
        for (int i = 0; i < 4; i++) {
            cp_async16(sa + soff[i], asrc[i] + k0);
            cp_async16(sB + soff[i], bsrc[i] + k0);
        }
    };

    issue(0); cp_commit();
    if (NK > 1) issue(1);
    cp_commit();

    for (int t = 0; t < NK; t++) {
        if (t + 1 < NK) cp_wait<1>(); else cp_wait<0>();
        __syncthreads();
        const int s = t % GSTAGES;
        const uint32_t sa = smA + s * T_BYTES;
        const uint32_t sB = smB + s * T_BYTES;

#pragma unroll
        for (int kg = 0; kg < 4; kg++) {       // 4 x k16 groups per BK=64
            uint32_t af[2][4];
#pragma unroll
            for (int mi = 0; mi < 2; mi++)
                ldsm_x4(af[mi][0], af[mi][1], af[mi][2], af[mi][3],
                        sa + ((abase[mi] + kg * 32) ^ lmask));
            uint32_t bf[8][2];
#pragma unroll
            for (int p = 0; p < 4; p++) {
                uint32_t r0, r1, r2, r3;
                ldsm_x4(r0, r1, r2, r3, sB + ((bbase[p] + kg * 32) ^ lmask));
                bf[2 * p][0] = r0; bf[2 * p + 1][0] = r1;
                bf[2 * p][1] = r2; bf[2 * p + 1][1] = r3;
            }
#pragma unroll
            for (int mi = 0; mi < 2; mi++)
#pragma unroll
                for (int nj = 0; nj < 8; nj++) {
                    asm volatile(
                        "mma.sync.aligned.m16n8k16.row.col.f32.f16.f16.f32 "
                        "{%0,%1,%2,%3}, {%4,%5,%6,%7}, {%8,%9}, {%0,%1,%2,%3};\n"
                        : "+f"(acc[mi][nj][0]), "+f"(acc[mi][nj][1]),
                          "+f"(acc[mi][nj][2]), "+f"(acc[mi][nj][3])
                        : "r"(af[mi][0]), "r"(af[mi][1]), "r"(af[mi][2]), "r"(af[mi][3]),
                          "r"(bf[nj][0]), "r"(bf[nj][1]));
                }
        }
        if (t + 2 < NK) issue(t + 2);
        cp_commit();
    }

    // ---- epilogue ----
#pragma unroll
    for (int mi = 0; mi < 2; mi++) {
#pragma unroll
        for (int nj = 0; nj < 8; nj++) {
            int m = m0 + wm * 32 + mi * 16 + g;
            int n = n0 + wn * 64 + nj * 8 + 2 * tig;
            if (n >= N) continue;
            float2 v0 = make_float2(acc[mi][nj][0], acc[mi][nj][1]);
            float2 v1 = make_float2(acc[mi][nj][2], acc[mi][nj][3]);
            if (EPI == EPI_SOFTPLUS) {
                float b0 = aux[n], b1 = aux[n + 1];
                v0.x += b0; v0.y += b1; v1.x += b0; v1.y += b1;
                v0.x = (v0.x > 20.f) ? v0.x : log1pf(__expf(v0.x));
                v0.y = (v0.y > 20.f) ? v0.y : log1pf(__expf(v0.y));
                v1.x = (v1.x > 20.f) ? v1.x : log1pf(__expf(v1.x));
                v1.y = (v1.y > 20.f) ? v1.y : log1pf(__expf(v1.y));
            } else if (EPI == EPI_RES) {
                float2 r0 = *reinterpret_cast<const float2*>(&aux[(size_t)m * ldc + n]);
                float2 r1 = *reinterpret_cast<const float2*>(&aux[(size_t)(m + 8) * ldc + n]);
                v0.x += r0.x; v0.y += r0.y; v1.x += r1.x; v1.y += r1.y;
            }
            *reinterpret_cast<float2*>(&C[(size_t)m * ldc + n]) = v0;
            *reinterpret_cast<float2*>(&C[(size_t)(m + 8) * ldc + n]) = v1;
        }
    }
}

// ---------------------------------------------------------------------------
// Split-K reduce -> g_xdbl (fp32, for scan) + g_xdbl_h (fp16, for dt GEMM)
// ---------------------------------------------------------------------------
__global__ __launch_bounds__(256)
void xdbl_reduce_kernel()
{
    const int i = blockIdx.x * 256 + threadIdx.x;
    const int n4 = MROWS * XDBLC / 4;
    if (i >= n4) return;
    const float4* p = reinterpret_cast<const float4*>(g_xpart);
    float4 a0 = p[i],          a1 = p[i + n4],     a2 = p[i + 2 * n4], a3 = p[i + 3 * n4];
    float4 a4 = p[i + 4 * n4], a5 = p[i + 5 * n4], a6 = p[i + 6 * n4], a7 = p[i + 7 * n4];
    float4 r;
    r.x = ((a0.x + a1.x) + (a2.x + a3.x)) + ((a4.x + a5.x) + (a6.x + a7.x));
    r.y = ((a0.y + a1.y) + (a2.y + a3.y)) + ((a4.y + a5.y) + (a6.y + a7.y));
    r.z = ((a0.z + a1.z) + (a2.z + a3.z)) + ((a4.z + a5.z) + (a6.z + a7.z));
    r.w = ((a0.w + a1.w) + (a2.w + a3.w)) + ((a4.w + a5.w) + (a6.w + a7.w));
    reinterpret_cast<float4*>(g_xdbl)[i] = r;
    uint2 o;
    o.x = h2u(__floats2half2_rn(r.x, r.y));
    o.y = h2u(__floats2half2_rn(r.z, r.w));
    reinterpret_cast<uint2*>(g_xdbl_h)[i] = o;
}

// ---------------------------------------------------------------------------
// Depthwise causal conv (width 4) + SiLU -> g_xc_h (fp16 only)
// ---------------------------------------------------------------------------
__global__ __launch_bounds__(256)
void conv_silu_kernel(const float* __restrict__ conv_w,
                      const float* __restrict__ conv_b)
{
    int idx = blockIdx.x * 256 + threadIdx.x;
    if (idx >= MROWS * DINNER) return;
    int d = idx & (DINNER - 1);
    int m = idx >> 11;
    int l = m & (SEQ - 1);
    int brow = m - l;
    float s = conv_b[d];
#pragma unroll
    for (int j = 0; j < DCONV; j++) {
        int ll = l + j - (DCONV - 1);
        if (ll >= 0)
            s = fmaf(conv_w[d * DCONV + j], g_xz[(size_t)(brow + ll) * XZCOLS + d], s);
    }
    float v = s * (1.f / (1.f + __expf(-s)));
    g_xc_h[idx] = __float2half_rn(v);
}

// ---------------------------------------------------------------------------
// SMEM-staged selective scan; xc read as fp16, y written as fp16
// ---------------------------------------------------------------------------
#define TC 64
__global__ __launch_bounds__(256)
void scan_kernel(const float* __restrict__ A_log,
                 const float* __restrict__ Dvec)
{
    __shared__ __align__(16) float dt_s[TC][16];
    __shared__ __align__(16) float xc_s[TC][16];
    __shared__ __align__(16) float z_s [TC][16];
    __shared__ __align__(16) float B_s [TC][16];
    __shared__ __align__(16) float C_s [TC][16];
    __shared__ __align__(16) float y_s [TC][16];

    const int tid = threadIdx.x;
    const int s   = tid & 15;
    const int c   = tid >> 4;
    const int d0  = (blockIdx.x * 16) & (DINNER - 1);
    const int b   = (blockIdx.x * 16) >> 11;
    const int d   = d0 + c;

    const float As = -__expf(A_log[d * DSTATE + s]);
    const float Dd = Dvec[d];

    const int r = tid >> 2, q = tid & 3;
    const size_t mb = (size_t)b * SEQ;

    float4 p_dt, p_z, p_B, p_C;
    uint2  p_xc;
    auto ldg_chunk = [&](int t0) {
        size_t m = mb + t0 + r;
        p_dt = *reinterpret_cast<const float4*>(&g_dt  [m * DINNER + d0 + q * 4]);
        p_xc = *reinterpret_cast<const uint2*>(&g_xc_h [m * DINNER + d0 + q * 4]);
        p_z  = *reinterpret_cast<const float4*>(&g_xz  [m * XZCOLS + DINNER + d0 + q * 4]);
        p_B  = *reinterpret_cast<const float4*>(&g_xdbl[m * XDBLC + DTRANK + q * 4]);
        p_C  = *reinterpret_cast<const float4*>(&g_xdbl[m * XDBLC + DTRANK + DSTATE + q * 4]);
    };
    auto sts_chunk = [&]() {
        *reinterpret_cast<float4*>(&dt_s[r][q * 4]) = p_dt;
        __half2 h0 = *reinterpret_cast<__half2*>(&p_xc.x);
        __half2 h1 = *reinterpret_cast<__half2*>(&p_xc.y);
        float2 f0 = __half22float2(h0);
        float2 f1 = __half22float2(h1);
        *reinterpret_cast<float4*>(&xc_s[r][q * 4]) =
            make_float4(f0.x, f0.y, f1.x, f1.y);
        *reinterpret_cast<float4*>(&z_s [r][q * 4]) = p_z;
        *reinterpret_cast<float4*>(&B_s [r][q * 4]) = p_B;
        *reinterpret_cast<float4*>(&C_s [r][q * 4]) = p_C;
    };

    ldg_chunk(0);
    sts_chunk();
    __syncthreads();

    float h = 0.f;
    for (int t0 = 0; t0 < SEQ; t0 += TC) {
        if (t0 + TC < SEQ) ldg_chunk(t0 + TC);
#pragma unroll 4
        for (int t = 0; t < TC; t++) {
            float dt_v = dt_s[t][c];
            float x_v  = xc_s[t][c];
            float Bv   = B_s [t][s];
            float Cv   = C_s [t][s];
            float dA = __expf(dt_v * As);
            h = fmaf(dA, h, dt_v * Bv * x_v);
            float p = h * Cv;
            p += __shfl_xor_sync(0xffffffffu, p, 1);
            p += __shfl_xor_sync(0xffffffffu, p, 2);
            p += __shfl_xor_sync(0xffffffffu, p, 4);
            p += __shfl_xor_sync(0xffffffffu, p, 8);
            if (s == 0) {
                float zv = z_s[t][c];
                float y  = fmaf(Dd, x_v, p);
                y *= zv * (1.f / (1.f + __expf(-zv)));
                y_s[t][c] = y;
            }
        }
        __syncthreads();
        {
            size_t m = mb + t0 + r;
            float4 yv = *reinterpret_cast<const float4*>(&y_s[r][q * 4]);
            uint2 o;
            o.x = h2u(__floats2half2_rn(yv.x, yv.y));
            o.y = h2u(__floats2half2_rn(yv.z, yv.w));
            *reinterpret_cast<uint2*>(&g_y_h[m * DINNER + d0 + q * 4]) = o;
        }
        if (t0 + TC < SEQ) sts_chunk();
        __syncthreads();
    }
}

// ---------------------------------------------------------------------------
// LayerNorm
// ---------------------------------------------------------------------------
__global__ __launch_bounds__(256)
void ln_kernel(const float* __restrict__ h,
               const float* __restrict__ gamma,
               const float* __restrict__ beta,
               float* __restrict__ out)
{
    int m = blockIdx.x;
    const float* row = h + (size_t)m * DMODEL;
    float s = 0.f, s2 = 0.f;
    for (int i = threadIdx.x; i < DMODEL; i += 256) {
        float v = row[i];
        s += v;
        s2 = fmaf(v, v, s2);
    }
#pragma unroll
    for (int o = 16; o; o >>= 1) {
        s  += __shfl_xor_sync(0xffffffffu, s,  o);
        s2 += __shfl_xor_sync(0xffffffffu, s2, o);
    }
    __shared__ float ss[8], ss2[8];
    int w = threadIdx.x >> 5, ln = threadIdx.x & 31;
    if (ln == 0) { ss[w] = s; ss2[w] = s2; }
    __syncthreads();
    s = 0.f; s2 = 0.f;
#pragma unroll
    for (int i = 0; i < 8; i++) { s += ss[i]; s2 += ss2[i]; }
    float mu  = s * (1.f / DMODEL);
    float var = s2 * (1.f / DMODEL) - mu * mu;
    float inv = rsqrtf(var + 1e-5f);
    for (int i = threadIdx.x; i < DMODEL; i += 256) {
        float v = row[i];
        out[(size_t)m * DMODEL + i] = (v - mu) * inv * gamma[i] + beta[i];
    }
}

// ---------------------------------------------------------------------------
// Launch
// ---------------------------------------------------------------------------
extern "C" void kernel_launch(void* const* d_in, const int* in_sizes, int n_in,
                              void* d_out, int out_size)
{
    const float* x          = (const float*)d_in[0];
    const float* in_proj_w  = (const float*)d_in[1];
    const float* conv_w     = (const float*)d_in[2];
    const float* conv_b     = (const float*)d_in[3];
    const float* x_proj_w   = (const float*)d_in[4];
    const float* dt_proj_w  = (const float*)d_in[5];
    const float* dt_proj_b  = (const float*)d_in[6];
    const float* A_log      = (const float*)d_in[7];
    const float* Dvec       = (const float*)d_in[8];
    const float* out_proj_w = (const float*)d_in[9];
    const float* ln_gamma   = (const float*)d_in[10];
    const float* ln_beta    = (const float*)d_in[11];
    float* out = (float*)d_out;

    float  *p_xz, *p_xpart, *p_dt, *p_h;
    __half *p_xch, *p_xdblh, *p_yh, *p_xh, *p_winh, *p_wouth, *p_wxh, *p_wdth;
    cudaGetSymbolAddress((void**)&p_xz,    g_xz);
    cudaGetSymbolAddress((void**)&p_xch,   g_xc_h);
    cudaGetSymbolAddress((void**)&p_xdblh, g_xdbl_h);
    cudaGetSymbolAddress((void**)&p_xpart, g_xpart);
    cudaGetSymbolAddress((void**)&p_dt,    g_dt);
    cudaGetSymbolAddress((void**)&p_yh,    g_y_h);
    cudaGetSymbolAddress((void**)&p_h,     g_h);
    cudaGetSymbolAddress((void**)&p_xh,    g_x_h);
    cudaGetSymbolAddress((void**)&p_winh,  g_win_h);
    cudaGetSymbolAddress((void**)&p_wouth, g_wout_h);
    cudaGetSymbolAddress((void**)&p_wxh,   g_wx_h);
    cudaGetSymbolAddress((void**)&p_wdth,  g_wdt_h);

    const int SMEM = GSTAGES * (16384 + 16384);   // 96 KB
    cudaFuncSetAttribute(hmma_gemm_nt<EPI_PLAIN>,
                         cudaFuncAttributeMaxDynamicSharedMemorySize, SMEM);
    cudaFuncSetAttribute(hmma_gemm_nt<EPI_SOFTPLUS>,
                         cudaFuncAttributeMaxDynamicSharedMemorySize, SMEM);
    cudaFuncSetAttribute(hmma_gemm_nt<EPI_RES>,
                         cudaFuncAttributeMaxDynamicSharedMemorySize, SMEM);

    // 1-3) fp16 conversions needed by in_proj (in_proj lands 4th = ncu slot)
    cvt_half_kernel<<<MROWS * DMODEL / 4 / 256, 256>>>(
        (const float4*)x, (uint2*)p_xh, MROWS * DMODEL / 4);
    cvt_half_kernel<<<XZCOLS * DMODEL / 4 / 256, 256>>>(
        (const float4*)in_proj_w, (uint2*)p_winh, XZCOLS * DMODEL / 4);
    cvt_half_kernel<<<DMODEL * DINNER / 4 / 256, 256>>>(
        (const float4*)out_proj_w, (uint2*)p_wouth, DMODEL * DINNER / 4);

    // 4) in_proj: xz = x @ W_in^T   (4096 x 4096, K=1024)
    hmma_gemm_nt<EPI_PLAIN><<<dim3(XZCOLS / 128, MROWS / 128, 1), 256, SMEM>>>(
        p_xh, DMODEL, p_winh, DMODEL, p_xz, XZCOLS,
        DMODEL, XZCOLS, nullptr, 0, 0);

    // 5-6) remaining weight conversions
    cvt_half_kernel<<<XDBLC * DINNER / 4 / 256, 256>>>(
        (const float4*)x_proj_w, (uint2*)p_wxh, XDBLC * DINNER / 4);
    cvt_half_kernel<<<DINNER * DTRANK / 4 / 256, 256>>>(
        (const float4*)dt_proj_w, (uint2*)p_wdth, DINNER * DTRANK / 4);

    // 7) conv + silu -> g_xc_h (fp16)
    conv_silu_kernel<<<(MROWS * DINNER + 255) / 256, 256>>>(conv_w, conv_b);

    // 8) x_proj (split-K=8): xc @ W_x^T  (4096 x 96, K=2048)
    hmma_gemm_nt<EPI_PLAIN><<<dim3(1, MROWS / 128, XSPLITK), 256, SMEM>>>(
        p_xch, DINNER, p_wxh, DINNER, p_xpart, XDBLC,
        DINNER / XSPLITK, XDBLC, nullptr,
        DINNER / XSPLITK, (size_t)MROWS * XDBLC);

    // 9) reduce partials -> g_xdbl (+ fp16 copy)
    xdbl_reduce_kernel<<<(MROWS * XDBLC / 4 + 255) / 256, 256>>>();

    // 10) dt = softplus(x_dbl[:, :64] @ W_dt^T + b)  (4096 x 2048, K=64)
    hmma_gemm_nt<EPI_SOFTPLUS><<<dim3(DINNER / 128, MROWS / 128, 1), 256, SMEM>>>(
        p_xdblh, XDBLC, p_wdth, DTRANK, p_dt, DINNER,
        DTRANK, DINNER, dt_proj_b, 0, 0);

    // 11) selective scan (+ D-skip, * silu(z)) -> g_y_h
    scan_kernel<<<(BATCH * DINNER) / 16, 256>>>(A_log, Dvec);

    // 12) out_proj + residual: h = y @ W_out^T + x   (4096 x 1024, K=2048)
    hmma_gemm_nt<EPI_RES><<<dim3(DMODEL / 128, MROWS / 128, 1), 256, SMEM>>>(
        p_yh, DINNER, p_wouth, DINNER, p_h, DMODEL,
        DINNER, DMODEL, x, 0, 0);

    // 13) LayerNorm -> out
    ln_kernel<<<MROWS, 256>>>(p_h, ln_gamma, ln_beta, out);
}

// round 15
// speedup vs baseline: 1.3573x; 1.0027x over previous
// R13: 2 CTAs/SM on fp16 GEMMs (launch_bounds 256,2) + fp16-only xc stream.
#include <cuda_runtime.h>
#include <cuda_fp16.h>
#include <cstdint>

#define BATCH   2
#define SEQ     2048
#define DMODEL  1024
#define DINNER  2048
#define DSTATE  16
#define DCONV   4
#define DTRANK  64
#define MROWS   (BATCH * SEQ)          // 4096
#define XZCOLS  (2 * DINNER)           // 4096
#define XDBLC   (DTRANK + 2 * DSTATE)  // 96
#define XSPLITK 8

// ---------------------------------------------------------------------------
// Scratch (device globals)
// ---------------------------------------------------------------------------
__device__ float  g_xz    [(size_t)MROWS * XZCOLS];   // [xi | z] fp32
__device__ __half g_xc_h  [(size_t)MROWS * DINNER];   // conv+silu fp16 (scan + x_proj A)
__device__ float  g_xdbl  [(size_t)MROWS * XDBLC];    // [dt_r | B | C] fp32 (scan)
__device__ __half g_xdbl_h[(size_t)MROWS * XDBLC];    // fp16 copy (dt A)
__device__ float  g_xpart [(size_t)XSPLITK * MROWS * XDBLC];
__device__ float  g_dt    [(size_t)MROWS * DINNER];   // softplus(dt) fp32 (scan)
__device__ __half g_y_h   [(size_t)MROWS * DINNER];   // scan out fp16 (out_proj A)
__device__ float  g_h     [(size_t)MROWS * DMODEL];   // out_proj + residual
// fp16 operands
__device__ __half g_x_h   [(size_t)MROWS * DMODEL];
__device__ __half g_win_h [(size_t)XZCOLS * DMODEL];
__device__ __half g_wout_h[(size_t)DMODEL * DINNER];
__device__ __half g_wx_h  [(size_t)XDBLC * DINNER];
__device__ __half g_wdt_h [(size_t)DINNER * DTRANK];

enum { EPI_PLAIN = 0, EPI_SOFTPLUS = 1, EPI_RES = 2 };

// ---------------------------------------------------------------------------
// PTX helpers
// ---------------------------------------------------------------------------
__device__ __forceinline__ void cp_async16(uint32_t dst, const void* src) {
    asm volatile("cp.async.cg.shared.global [%0], [%1], 16;\n" :: "r"(dst), "l"(src));
}
__device__ __forceinline__ void cp_commit() {
    asm volatile("cp.async.commit_group;\n" ::: "memory");
}
template <int N> __device__ __forceinline__ void cp_wait() {
    asm volatile("cp.async.wait_group %0;\n" :: "n"(N) : "memory");
}
__device__ __forceinline__ void ldsm_x4(uint32_t& r0, uint32_t& r1,
                                        uint32_t& r2, uint32_t& r3, uint32_t addr) {
    asm volatile("ldmatrix.sync.aligned.m8n8.x4.shared.b16 {%0,%1,%2,%3}, [%4];\n"
                 : "=r"(r0), "=r"(r1), "=r"(r2), "=r"(r3) : "r"(addr));
}
__device__ __forceinline__ uint32_t h2u(__half2 h) {
    return *reinterpret_cast<uint32_t*>(&h);
}

// ---------------------------------------------------------------------------
// fp32 -> fp16 (rne) conversion kernel
// ---------------------------------------------------------------------------
__global__ __launch_bounds__(256)
void cvt_half_kernel(const float4* __restrict__ src, uint2* __restrict__ dst, int n4)
{
    int i = blockIdx.x * 256 + threadIdx.x;
    if (i >= n4) return;
    float4 v = src[i];
    uint2 o;
    o.x = h2u(__floats2half2_rn(v.x, v.y));
    o.y = h2u(__floats2half2_rn(v.z, v.w));
    dst[i] = o;
}

// ---------------------------------------------------------------------------
// fp16 tensor-core NT GEMM: C[M,N] = A[M,K]*B[N,K]^T, fp32 accum/output.
// BM=128, BN=128, BK=64 (128B rows, SW128 XOR swizzle), 3-stage cp.async,
// ldmatrix.x4, mma.sync.m16n8k16. 256 threads = 8 warps (4m x 2n), warp
// tile 32x64. launch_bounds(256,2): <=128 regs so 2 CTAs/SM co-reside
// (2 x 96KB = 192KB < 227KB). M%128==0, K%64==0; N<128 handled.
// ---------------------------------------------------------------------------
#define GSTAGES 3
template <int EPI>
__global__ __launch_bounds__(256, 2)
void hmma_gemm_nt(const __half* __restrict__ A, int lda,
                  const __half* __restrict__ B, int ldb,
                  float* __restrict__ C, int ldc,
                  int K, int N, const float* __restrict__ aux,
                  int kz, size_t cz)
{
    constexpr int BK = 64;
    constexpr int T_BYTES = 128 * BK * 2;    // 16 KB per operand tile
    extern __shared__ __align__(16) char smem[];
    const uint32_t smem_u = (uint32_t)__cvta_generic_to_shared(smem);
    const uint32_t smA = smem_u;
    const uint32_t smB = smem_u + GSTAGES * T_BYTES;

    A += (size_t)blockIdx.z * kz;
    B += (size_t)blockIdx.z * kz;
    C += (size_t)blockIdx.z * cz;

    const int tid  = threadIdx.x, lane = tid & 31, wid = tid >> 5;
    const int g    = lane >> 2, tig = lane & 3;
    const int wm   = wid & 3, wn = wid >> 2;
    const int m0   = blockIdx.y * 128, n0 = blockIdx.x * 128;

    // cp.async: 128 rows x 128B (8 x 16B chunks) per operand, 4 chunks/thread
    const __half* asrc[4]; const __half* bsrc[4]; uint32_t soff[4];
#pragma unroll
    for (int i = 0; i < 4; i++) {
        int id = tid + i * 256, r = id >> 3, ch = id & 7;
        soff[i] = (uint32_t)((r * 128 + ch * 16) ^ ((r & 7) << 4));
        asrc[i] = A + (size_t)(m0 + r) * lda + ch * 8;
        int br = n0 + r; if (br > N - 1) br = N - 1;
        bsrc[i] = B + (size_t)br * ldb + ch * 8;
    }

    // ldmatrix addressing (k16 = 32B per kg step)
    const int lrow  = (lane & 7) + ((lane >> 3) & 1) * 8;
    const int lkb   = ((lane >> 4) & 1) * 16;
    const uint32_t lmask = (uint32_t)((lane & 7) << 4);
    uint32_t abase[2], bbase[4];
#pragma unroll
    for (int mi = 0; mi < 2; mi++)
        abase[mi] = (uint32_t)((wm * 32 + mi * 16 + lrow) * 128 + lkb);
#pragma unroll
    for (int p = 0; p < 4; p++)
        bbase[p] = (uint32_t)((wn * 64 + p * 16 + lrow) * 128 + lkb);

    float acc[2][8][4];
#pragma unroll
    for (int mi = 0; mi < 2; mi++)
#pragma unroll
        for (int nj = 0; nj < 8; nj++)
#pragma unroll
            for (int q = 0; q < 4; q++) acc[mi][nj][q] = 0.f;

    const int NK = K / BK;
    auto issue = [&](int t) {
        const int s = t % GSTAGES;
        const uint32_t sa = smA + s * T_BYTES;
        const uint32_t sB = smB + s * T_BYTES;
        const int k0 = t * BK;
#pragma unroll
        for (int i = 0; i < 4; i++) {
            cp_async16(sa + soff[i], asrc[i] + k0);
            cp_async16(sB + soff[i], bsrc[i] + k0);
        }
    };

    issue(0); cp_commit();
    if (NK > 1) issue(1);
    cp_commit();

    for (int t = 0; t < NK; t++) {
        if (t + 1 < NK) cp_wait<1>(); else cp_wait<0>();
        __syncthreads();
        const int s = t % GSTAGES;
        const uint32_t sa = smA + s * T_BYTES;
        const uint32_t sB = smB + s * T_BYTES;

#pragma unroll
        for (int kg = 0; kg < 4; kg++) {       // 4 x k16 groups per BK=64
            uint32_t af[2][4];
#pragma unroll
            for (int mi = 0; mi < 2; mi++)
                ldsm_x4(af[mi][0], af[mi][1], af[mi][2], af[mi][3],
                        sa + ((abase[mi] + kg * 32) ^ lmask));
            uint32_t bf[8][2];
#pragma unroll
            for (int p = 0; p < 4; p++) {
                uint32_t r0, r1, r2, r3;
                ldsm_x4(r0, r1, r2, r3, sB + ((bbase[p] + kg * 32) ^ lmask));
                bf[2 * p][0] = r0; bf[2 * p + 1][0] = r1;
                bf[2 * p][1] = r2; bf[2 * p + 1][1] = r3;
            }
#pragma unroll
            for (int mi = 0; mi < 2; mi++)
#pragma unroll
                for (int nj = 0; nj < 8; nj++) {
                    asm volatile(
                        "mma.sync.aligned.m16n8k16.row.col.f32.f16.f16.f32 "
                        "{%0,%1,%2,%3}, {%4,%5,%6,%7}, {%8,%9}, {%0,%1,%2,%3};\n"
                        : "+f"(acc[mi][nj][0]), "+f"(acc[mi][nj][1]),
                          "+f"(acc[mi][nj][2]), "+f"(acc[mi][nj][3])
                        : "r"(af[mi][0]), "r"(af[mi][1]), "r"(af[mi][2]), "r"(af[mi][3]),
                          "r"(bf[nj][0]), "r"(bf[nj][1]));
                }
        }
        if (t + 2 < NK) issue(t + 2);
        cp_commit();
    }

    // ---- epilogue ----
#pragma unroll
    for (int mi = 0; mi < 2; mi++) {
#pragma unroll
        for (int nj = 0; nj < 8; nj++) {
            int m = m0 + wm * 32 + mi * 16 + g;
            int n = n0 + wn * 64 + nj * 8 + 2 * tig;
            if (n >= N) continue;
            float2 v0 = make_float2(acc[mi][nj][0], acc[mi][nj][1]);
            float2 v1 = make_float2(acc[mi][nj][2], acc[mi][nj][3]);
            if (EPI == EPI_SOFTPLUS) {
                float b0 = aux[n], b1 = aux[n + 1];
                v0.x += b0; v0.y += b1; v1.x += b0; v1.y += b1;
                v0.x = (v0.x > 20.f) ? v0.x : log1pf(__expf(v0.x));
                v0.y = (v0.y > 20.f) ? v0.y : log1pf(__expf(v0.y));
                v1.x = (v1.x > 20.f) ? v1.x : log1pf(__expf(v1.x));
                v1.y = (v1.y > 20.f) ? v1.y : log1pf(__expf(v1.y));
            } else if (EPI == EPI_RES) {
                float2 r0 = *reinterpret_cast<const float2*>(&aux[(size_t)m * ldc + n]);
                float2 r1 = *reinterpret_cast<const float2*>(&aux[(size_t)(m + 8) * ldc + n]);
                v0.x += r0.x; v0.y += r0.y; v1.x += r1.x; v1.y += r1.y;
            }
            *reinterpret_cast<float2*>(&C[(size_t)m * ldc + n]) = v0;
            *reinterpret_cast<float2*>(&C[(size_t)(m + 8) * ldc + n]) = v1;
        }
    }
}

// ---------------------------------------------------------------------------
// Split-K reduce -> g_xdbl (fp32, for scan) + g_xdbl_h (fp16, for dt GEMM)
// ---------------------------------------------------------------------------
__global__ __launch_bounds__(256)
void xdbl_reduce_kernel()
{
    const int i = blockIdx.x * 256 + threadIdx.x;
    const int n4 = MROWS * XDBLC / 4;
    if (i >= n4) return;
    const float4* p = reinterpret_cast<const float4*>(g_xpart);
    float4 a0 = p[i],          a1 = p[i + n4],     a2 = p[i + 2 * n4], a3 = p[i + 3 * n4];
    float4 a4 = p[i + 4 * n4], a5 = p[i + 5 * n4], a6 = p[i + 6 * n4], a7 = p[i + 7 * n4];
    float4 r;
    r.x = ((a0.x + a1.x) + (a2.x + a3.x)) + ((a4.x + a5.x) + (a6.x + a7.x));
    r.y = ((a0.y + a1.y) + (a2.y + a3.y)) + ((a4.y + a5.y) + (a6.y + a7.y));
    r.z = ((a0.z + a1.z) + (a2.z + a3.z)) + ((a4.z + a5.z) + (a6.z + a7.z));
    r.w = ((a0.w + a1.w) + (a2.w + a3.w)) + ((a4.w + a5.w) + (a6.w + a7.w));
    reinterpret_cast<float4*>(g_xdbl)[i] = r;
    uint2 o;
    o.x = h2u(__floats2half2_rn(r.x, r.y));
    o.y = h2u(__floats2half2_rn(r.z, r.w));
    reinterpret_cast<uint2*>(g_xdbl_h)[i] = o;
}

// ---------------------------------------------------------------------------
// Depthwise causal conv (width 4) + SiLU -> g_xc_h (fp16 only)
// ---------------------------------------------------------------------------
__global__ __launch_bounds__(256)
void conv_silu_kernel(const float* __restrict__ conv_w,
                      const float* __restrict__ conv_b)
{
    int idx = blockIdx.x * 256 + threadIdx.x;
    if (idx >= MROWS * DINNER) return;
    int d = idx & (DINNER - 1);
    int m = idx >> 11;
    int l = m & (SEQ - 1);
    int brow = m - l;
    float s = conv_b[d];
#pragma unroll
    for (int j = 0; j < DCONV; j++) {
        int ll = l + j - (DCONV - 1);
        if (ll >= 0)
            s = fmaf(conv_w[d * DCONV + j], g_xz[(size_t)(brow + ll) * XZCOLS + d], s);
    }
    float v = s * (1.f / (1.f + __expf(-s)));
    g_xc_h[idx] = __float2half_rn(v);
}

// ---------------------------------------------------------------------------
// SMEM-staged selective scan; xc read as fp16, y written as fp16
// ---------------------------------------------------------------------------
#define TC 64
__global__ __launch_bounds__(256)
void scan_kernel(const float* __restrict__ A_log,
                 const float* __restrict__ Dvec)
{
    __shared__ __align__(16) float dt_s[TC][16];
    __shared__ __align__(16) float xc_s[TC][16];
    __shared__ __align__(16) float z_s [TC][16];
    __shared__ __align__(16) float B_s [TC][16];
    __shared__ __align__(16) float C_s [TC][16];
    __shared__ __align__(16) float y_s [TC][16];

    const int tid = threadIdx.x;
    const int s   = tid & 15;
    const int c   = tid >> 4;
    const int d0  = (blockIdx.x * 16) & (DINNER - 1);
    const int b   = (blockIdx.x * 16) >> 11;
    const int d   = d0 + c;

    const float As = -__expf(A_log[d * DSTATE + s]);
    const float Dd = Dvec[d];

    const int r = tid >> 2, q = tid & 3;
    const size_t mb = (size_t)b * SEQ;

    float4 p_dt, p_z, p_B, p_C;
    uint2  p_xc;
    auto ldg_chunk = [&](int t0) {
        size_t m = mb + t0 + r;
        p_dt = *reinterpret_cast<const float4*>(&g_dt  [m * DINNER + d0 + q * 4]);
        p_xc = *reinterpret_cast<const uint2*>(&g_xc_h [m * DINNER + d0 + q * 4]);
        p_z  = *reinterpret_cast<const float4*>(&g_xz  [m * XZCOLS + DINNER + d0 + q * 4]);
        p_B  = *reinterpret_cast<const float4*>(&g_xdbl[m * XDBLC + DTRANK + q * 4]);
        p_C  = *reinterpret_cast<const float4*>(&g_xdbl[m * XDBLC + DTRANK + DSTATE + q * 4]);
    };
    auto sts_chunk = [&]() {
        *reinterpret_cast<float4*>(&dt_s[r][q * 4]) = p_dt;
        __half2 h0 = *reinterpret_cast<__half2*>(&p_xc.x);
        __half2 h1 = *reinterpret_cast<__half2*>(&p_xc.y);
        float2 f0 = __half22float2(h0);
        float2 f1 = __half22float2(h1);
        *reinterpret_cast<float4*>(&xc_s[r][q * 4]) =
            make_float4(f0.x, f0.y, f1.x, f1.y);
        *reinterpret_cast<float4*>(&z_s [r][q * 4]) = p_z;
        *reinterpret_cast<float4*>(&B_s [r][q * 4]) = p_B;
        *reinterpret_cast<float4*>(&C_s [r][q * 4]) = p_C;
    };

    ldg_chunk(0);
    sts_chunk();
    __syncthreads();

    float h = 0.f;
    for (int t0 = 0; t0 < SEQ; t0 += TC) {
        if (t0 + TC < SEQ) ldg_chunk(t0 + TC);
#pragma unroll 4
        for (int t = 0; t < TC; t++) {
            float dt_v = dt_s[t][c];
            float x_v  = xc_s[t][c];
            float Bv   = B_s [t][s];
            float Cv   = C_s [t][s];
            float dA = __expf(dt_v * As);
            h = fmaf(dA, h, dt_v * Bv * x_v);
            float p = h * Cv;
            p += __shfl_xor_sync(0xffffffffu, p, 1);
            p += __shfl_xor_sync(0xffffffffu, p, 2);
            p += __shfl_xor_sync(0xffffffffu, p, 4);
            p += __shfl_xor_sync(0xffffffffu, p, 8);
            if (s == 0) {
                float zv = z_s[t][c];
                float y  = fmaf(Dd, x_v, p);
                y *= zv * (1.f / (1.f + __expf(-zv)));
                y_s[t][c] = y;
            }
        }
        __syncthreads();
        {
            size_t m = mb + t0 + r;
            float4 yv = *reinterpret_cast<const float4*>(&y_s[r][q * 4]);
            uint2 o;
            o.x = h2u(__floats2half2_rn(yv.x, yv.y));
            o.y = h2u(__floats2half2_rn(yv.z, yv.w));
            *reinterpret_cast<uint2*>(&g_y_h[m * DINNER + d0 + q * 4]) = o;
        }
        if (t0 + TC < SEQ) sts_chunk();
        __syncthreads();
    }
}

// ---------------------------------------------------------------------------
// LayerNorm
// ---------------------------------------------------------------------------
__global__ __launch_bounds__(256)
void ln_kernel(const float* __restrict__ h,
               const float* __restrict__ gamma,
               const float* __restrict__ beta,
               float* __restrict__ out)
{
    int m = blockIdx.x;
    const float* row = h + (size_t)m * DMODEL;
    float s = 0.f, s2 = 0.f;
    for (int i = threadIdx.x; i < DMODEL; i += 256) {
        float v = row[i];
        s += v;
        s2 = fmaf(v, v, s2);
    }
#pragma unroll
    for (int o = 16; o; o >>= 1) {
        s  += __shfl_xor_sync(0xffffffffu, s,  o);
        s2 += __shfl_xor_sync(0xffffffffu, s2, o);
    }
    __shared__ float ss[8], ss2[8];
    int w = threadIdx.x >> 5, ln = threadIdx.x & 31;
    if (ln == 0) { ss[w] = s; ss2[w] = s2; }
    __syncthreads();
    s = 0.f; s2 = 0.f;
#pragma unroll
    for (int i = 0; i < 8; i++) { s += ss[i]; s2 += ss2[i]; }
    float mu  = s * (1.f / DMODEL);
    float var = s2 * (1.f / DMODEL) - mu * mu;
    float inv = rsqrtf(var + 1e-5f);
    for (int i = threadIdx.x; i < DMODEL; i += 256) {
        float v = row[i];
        out[(size_t)m * DMODEL + i] = (v - mu) * inv * gamma[i] + beta[i];
    }
}

// ---------------------------------------------------------------------------
// Launch
// ---------------------------------------------------------------------------
extern "C" void kernel_launch(void* const* d_in, const int* in_sizes, int n_in,
                              void* d_out, int out_size)
{
    const float* x          = (const float*)d_in[0];
    const float* in_proj_w  = (const float*)d_in[1];
    const float* conv_w     = (const float*)d_in[2];
    const float* conv_b     = (const float*)d_in[3];
    const float* x_proj_w   = (const float*)d_in[4];
    const float* dt_proj_w  = (const float*)d_in[5];
    const float* dt_proj_b  = (const float*)d_in[6];
    const float* A_log      = (const float*)d_in[7];
    const float* Dvec       = (const float*)d_in[8];
    const float* out_proj_w = (const float*)d_in[9];
    const float* ln_gamma   = (const float*)d_in[10];
    const float* ln_beta    = (const float*)d_in[11];
    float* out = (float*)d_out;

    float  *p_xz, *p_xpart, *p_dt, *p_h;
    __half *p_xch, *p_xdblh, *p_yh, *p_xh, *p_winh, *p_wouth, *p_wxh, *p_wdth;
    cudaGetSymbolAddress((void**)&p_xz,    g_xz);
    cudaGetSymbolAddress((void**)&p_xch,   g_xc_h);
    cudaGetSymbolAddress((void**)&p_xdblh, g_xdbl_h);
    cudaGetSymbolAddress((void**)&p_xpart, g_xpart);
    cudaGetSymbolAddress((void**)&p_dt,    g_dt);
    cudaGetSymbolAddress((void**)&p_yh,    g_y_h);
    cudaGetSymbolAddress((void**)&p_h,     g_h);
    cudaGetSymbolAddress((void**)&p_xh,    g_x_h);
    cudaGetSymbolAddress((void**)&p_winh,  g_win_h);
    cudaGetSymbolAddress((void**)&p_wouth, g_wout_h);
    cudaGetSymbolAddress((void**)&p_wxh,   g_wx_h);
    cudaGetSymbolAddress((void**)&p_wdth,  g_wdt_h);

    const int SMEM = GSTAGES * (16384 + 16384);   // 96 KB
    cudaFuncSetAttribute(hmma_gemm_nt<EPI_PLAIN>,
                         cudaFuncAttributeMaxDynamicSharedMemorySize, SMEM);
    cudaFuncSetAttribute(hmma_gemm_nt<EPI_SOFTPLUS>,
                         cudaFuncAttributeMaxDynamicSharedMemorySize, SMEM);
    cudaFuncSetAttribute(hmma_gemm_nt<EPI_RES>,
                         cudaFuncAttributeMaxDynamicSharedMemorySize, SMEM);

    // 1-3) fp16 conversions needed by in_proj (in_proj lands 4th = ncu slot)
    cvt_half_kernel<<<MROWS * DMODEL / 4 / 256, 256>>>(
        (const float4*)x, (uint2*)p_xh, MROWS * DMODEL / 4);
    cvt_half_kernel<<<XZCOLS * DMODEL / 4 / 256, 256>>>(
        (const float4*)in_proj_w, (uint2*)p_winh, XZCOLS * DMODEL / 4);
    cvt_half_kernel<<<DMODEL * DINNER / 4 / 256, 256>>>(
        (const float4*)out_proj_w, (uint2*)p_wouth, DMODEL * DINNER / 4);

    // 4) in_proj: xz = x @ W_in^T   (4096 x 4096, K=1024)
    hmma_gemm_nt<EPI_PLAIN><<<dim3(XZCOLS / 128, MROWS / 128, 1), 256, SMEM>>>(
        p_xh, DMODEL, p_winh, DMODEL, p_xz, XZCOLS,
        DMODEL, XZCOLS, nullptr, 0, 0);

    // 5-6) remaining weight conversions
    cvt_half_kernel<<<XDBLC * DINNER / 4 / 256, 256>>>(
        (const float4*)x_proj_w, (uint2*)p_wxh, XDBLC * DINNER / 4);
    cvt_half_kernel<<<DINNER * DTRANK / 4 / 256, 256>>>(
        (const float4*)dt_proj_w, (uint2*)p_wdth, DINNER * DTRANK / 4);

    // 7) conv + silu -> g_xc_h (fp16)
    conv_silu_kernel<<<(MROWS * DINNER + 255) / 256, 256>>>(conv_w, conv_b);

    // 8) x_proj (split-K=8): xc @ W_x^T  (4096 x 96, K=2048)
    hmma_gemm_nt<EPI_PLAIN><<<dim3(1, MROWS / 128, XSPLITK), 256, SMEM>>>(
        p_xch, DINNER, p_wxh, DINNER, p_xpart, XDBLC,
        DINNER / XSPLITK, XDBLC, nullptr,
        DINNER / XSPLITK, (size_t)MROWS * XDBLC);

    // 9) reduce partials -> g_xdbl (+ fp16 copy)
    xdbl_reduce_kernel<<<(MROWS * XDBLC / 4 + 255) / 256, 256>>>();

    // 10) dt = softplus(x_dbl[:, :64] @ W_dt^T + b)  (4096 x 2048, K=64)
    hmma_gemm_nt<EPI_SOFTPLUS><<<dim3(DINNER / 128, MROWS / 128, 1), 256, SMEM>>>(
        p_xdblh, XDBLC, p_wdth, DTRANK, p_dt, DINNER,
        DTRANK, DINNER, dt_proj_b, 0, 0);

    // 11) selective scan (+ D-skip, * silu(z)) -> g_y_h
    scan_kernel<<<(BATCH * DINNER) / 16, 256>>>(A_log, Dvec);

    // 12) out_proj + residual: h = y @ W_out^T + x   (4096 x 1024, K=2048)
    hmma_gemm_nt<EPI_RES><<<dim3(DMODEL / 128, MROWS / 128, 1), 256, SMEM>>>(
        p_yh, DINNER, p_wouth, DINNER, p_h, DMODEL,
        DINNER, DMODEL, x, 0, 0);

    // 13) LayerNorm -> out
    ln_kernel<<<MROWS, 256>>>(p_h, ln_gamma, ln_beta, out);
}

// round 16
// speedup vs baseline: 1.3647x; 1.0054x over previous
// R16: GEMM mainloop reorder — issue stage t+2 right after the barrier (before compute).
#include <cuda_runtime.h>
#include <cuda_fp16.h>
#include <cstdint>

#define BATCH   2
#define SEQ     2048
#define DMODEL  1024
#define DINNER  2048
#define DSTATE  16
#define DCONV   4
#define DTRANK  64
#define MROWS   (BATCH * SEQ)          // 4096
#define XZCOLS  (2 * DINNER)           // 4096
#define XDBLC   (DTRANK + 2 * DSTATE)  // 96
#define XSPLITK 8

// ---------------------------------------------------------------------------
// Scratch (device globals)
// ---------------------------------------------------------------------------
__device__ float  g_xz    [(size_t)MROWS * XZCOLS];   // [xi | z] fp32
__device__ __half g_xc_h  [(size_t)MROWS * DINNER];   // conv+silu fp16 (scan + x_proj A)
__device__ float  g_xdbl  [(size_t)MROWS * XDBLC];    // [dt_r | B | C] fp32 (scan)
__device__ __half g_xdbl_h[(size_t)MROWS * XDBLC];    // fp16 copy (dt A)
__device__ float  g_xpart [(size_t)XSPLITK * MROWS * XDBLC];
__device__ float  g_dt    [(size_t)MROWS * DINNER];   // softplus(dt) fp32 (scan)
__device__ __half g_y_h   [(size_t)MROWS * DINNER];   // scan out fp16 (out_proj A)
__device__ float  g_h     [(size_t)MROWS * DMODEL];   // out_proj + residual
// fp16 operands
__device__ __half g_x_h   [(size_t)MROWS * DMODEL];
__device__ __half g_win_h [(size_t)XZCOLS * DMODEL];
__device__ __half g_wout_h[(size_t)DMODEL * DINNER];
__device__ __half g_wx_h  [(size_t)XDBLC * DINNER];
__device__ __half g_wdt_h [(size_t)DINNER * DTRANK];

enum { EPI_PLAIN = 0, EPI_SOFTPLUS = 1, EPI_RES = 2 };

// ---------------------------------------------------------------------------
// PTX helpers
// ---------------------------------------------------------------------------
__device__ __forceinline__ void cp_async16(uint32_t dst, const void* src) {
    asm volatile("cp.async.cg.shared.global [%0], [%1], 16;\n" :: "r"(dst), "l"(src));
}
__device__ __forceinline__ void cp_commit() {
    asm volatile("cp.async.commit_group;\n" ::: "memory");
}
template <int N> __device__ __forceinline__ void cp_wait() {
    asm volatile("cp.async.wait_group %0;\n" :: "n"(N) : "memory");
}
__device__ __forceinline__ void ldsm_x4(uint32_t& r0, uint32_t& r1,
                                        uint32_t& r2, uint32_t& r3, uint32_t addr) {
    asm volatile("ldmatrix.sync.aligned.m8n8.x4.shared.b16 {%0,%1,%2,%3}, [%4];\n"
                 : "=r"(r0), "=r"(r1), "=r"(r2), "=r"(r3) : "r"(addr));
}
__device__ __forceinline__ uint32_t h2u(__half2 h) {
    return *reinterpret_cast<uint32_t*>(&h);
}

// ---------------------------------------------------------------------------
// fp32 -> fp16 (rne) conversion kernel
// ---------------------------------------------------------------------------
__global__ __launch_bounds__(256)
void cvt_half_kernel(const float4* __restrict__ src, uint2* __restrict__ dst, int n4)
{
    int i = blockIdx.x * 256 + threadIdx.x;
    if (i >= n4) return;
    float4 v = src[i];
    uint2 o;
    o.x = h2u(__floats2half2_rn(v.x, v.y));
    o.y = h2u(__floats2half2_rn(v.z, v.w));
    dst[i] = o;
}

// ---------------------------------------------------------------------------
// fp16 tensor-core NT GEMM: C[M,N] = A[M,K]*B[N,K]^T, fp32 accum/output.
// BM=128, BN=128, BK=64 (128B rows, SW128 XOR swizzle), 3-stage cp.async,
// ldmatrix.x4, mma.sync.m16n8k16. 256 threads = 8 warps (4m x 2n), warp
// tile 32x64. launch_bounds(256,2) -> 2 CTAs/SM (2x96KB smem, <=128 regs).
// Mainloop issues the t+2 copy right after the tile barrier so each cp.async
// overlaps ~2 compute tiles. Group FIFO: tile t's data = group t; wait<1>
// at iter t retires groups 0..t; empty tail commits preserve numbering.
// ---------------------------------------------------------------------------
#define GSTAGES 3
template <int EPI>
__global__ __launch_bounds__(256, 2)
void hmma_gemm_nt(const __half* __restrict__ A, int lda,
                  const __half* __restrict__ B, int ldb,
                  float* __restrict__ C, int ldc,
                  int K, int N, const float* __restrict__ aux,
                  int kz, size_t cz)
{
    constexpr int BK = 64;
    constexpr int T_BYTES = 128 * BK * 2;    // 16 KB per operand tile
    extern __shared__ __align__(16) char smem[];
    const uint32_t smem_u = (uint32_t)__cvta_generic_to_shared(smem);
    const uint32_t smA = smem_u;
    const uint32_t smB = smem_u + GSTAGES * T_BYTES;

    A += (size_t)blockIdx.z * kz;
    B += (size_t)blockIdx.z * kz;
    C += (size_t)blockIdx.z * cz;

    const int tid  = threadIdx.x, lane = tid & 31, wid = tid >> 5;
    const int g    = lane >> 2, tig = lane & 3;
    const int wm   = wid & 3, wn = wid >> 2;
    const int m0   = blockIdx.y * 128, n0 = blockIdx.x * 128;

    // cp.async: 128 rows x 128B (8 x 16B chunks) per operand, 4 chunks/thread
    const __half* asrc[4]; const __half* bsrc[4]; uint32_t soff[4];
#pragma unroll
    for (int i = 0; i < 4; i++) {
        int id = tid + i * 256, r = id >> 3, ch = id & 7;
        soff[i] = (uint32_t)((r * 128 + ch * 16) ^ ((r & 7) << 4));
        asrc[i] = A + (size_t)(m0 + r) * lda + ch * 8;
        int br = n0 + r; if (br > N - 1) br = N - 1;
        bsrc[i] = B + (size_t)br * ldb + ch * 8;
    }

    // ldmatrix addressing (k16 = 32B per kg step)
    const int lrow  = (lane & 7) + ((lane >> 3) & 1) * 8;
    const int lkb   = ((lane >> 4) & 1) * 16;
    const uint32_t lmask = (uint32_t)((lane & 7) << 4);
    uint32_t abase[2], bbase[4];
#pragma unroll
    for (int mi = 0; mi < 2; mi++)
        abase[mi] = (uint32_t)((wm * 32 + mi * 16 + lrow) * 128 + lkb);
#pragma unroll
    for (int p = 0; p < 4; p++)
        bbase[p] = (uint32_t)((wn * 64 + p * 16 + lrow) * 128 + lkb);

    float acc[2][8][4];
#pragma unroll
    for (int mi = 0; mi < 2; mi++)
#pragma unroll
        for (int nj = 0; nj < 8; nj++)
#pragma unroll
            for (int q = 0; q < 4; q++) acc[mi][nj][q] = 0.f;

    const int NK = K / BK;
    auto issue = [&](int t) {
        const int s = t % GSTAGES;
        const uint32_t sa = smA + s * T_BYTES;
        const uint32_t sB = smB + s * T_BYTES;
        const int k0 = t * BK;
#pragma unroll
        for (int i = 0; i < 4; i++) {
            cp_async16(sa + soff[i], asrc[i] + k0);
            cp_async16(sB + soff[i], bsrc[i] + k0);
        }
    };

    issue(0); cp_commit();
    if (NK > 1) issue(1);
    cp_commit();

    for (int t = 0; t < NK; t++) {
        if (t + 1 < NK) cp_wait<1>(); else cp_wait<0>();
        __syncthreads();
        // issue t+2 NOW (stage (t-1)%3 freed by the barrier) -> copy overlaps
        // the whole compute of tile t plus the next iteration's.
        if (t + 2 < NK) issue(t + 2);
        cp_commit();

        const int s = t % GSTAGES;
        const uint32_t sa = smA + s * T_BYTES;
        const uint32_t sB = smB + s * T_BYTES;

#pragma unroll
        for (int kg = 0; kg < 4; kg++) {       // 4 x k16 groups per BK=64
            uint32_t af[2][4];
#pragma unroll
            for (int mi = 0; mi < 2; mi++)
                ldsm_x4(af[mi][0], af[mi][1], af[mi][2], af[mi][3],
                        sa + ((abase[mi] + kg * 32) ^ lmask));
            uint32_t bf[8][2];
#pragma unroll
            for (int p = 0; p < 4; p++) {
                uint32_t r0, r1, r2, r3;
                ldsm_x4(r0, r1, r2, r3, sB + ((bbase[p] + kg * 32) ^ lmask));
                bf[2 * p][0] = r0; bf[2 * p + 1][0] = r1;
                bf[2 * p][1] = r2; bf[2 * p + 1][1] = r3;
            }
#pragma unroll
            for (int mi = 0; mi < 2; mi++)
#pragma unroll
                for (int nj = 0; nj < 8; nj++) {
                    asm volatile(
                        "mma.sync.aligned.m16n8k16.row.col.f32.f16.f16.f32 "
                        "{%0,%1,%2,%3}, {%4,%5,%6,%7}, {%8,%9}, {%0,%1,%2,%3};\n"
                        : "+f"(acc[mi][nj][0]), "+f"(acc[mi][nj][1]),
                          "+f"(acc[mi][nj][2]), "+f"(acc[mi][nj][3])
                        : "r"(af[mi][0]), "r"(af[mi][1]), "r"(af[mi][2]), "r"(af[mi][3]),
                          "r"(bf[nj][0]), "r"(bf[nj][1]));
                }
        }
    }

    // ---- epilogue ----
#pragma unroll
    for (int mi = 0; mi < 2; mi++) {
#pragma unroll
        for (int nj = 0; nj < 8; nj++) {
            int m = m0 + wm * 32 + mi * 16 + g;
            int n = n0 + wn * 64 + nj * 8 + 2 * tig;
            if (n >= N) continue;
            float2 v0 = make_float2(acc[mi][nj][0], acc[mi][nj][1]);
            float2 v1 = make_float2(acc[mi][nj][2], acc[mi][nj][3]);
            if (EPI == EPI_SOFTPLUS) {
                float b0 = aux[n], b1 = aux[n + 1];
                v0.x += b0; v0.y += b1; v1.x += b0; v1.y += b1;
                v0.x = (v0.x > 20.f) ? v0.x : log1pf(__expf(v0.x));
                v0.y = (v0.y > 20.f) ? v0.y : log1pf(__expf(v0.y));
                v1.x = (v1.x > 20.f) ? v1.x : log1pf(__expf(v1.x));
                v1.y = (v1.y > 20.f) ? v1.y : log1pf(__expf(v1.y));
            } else if (EPI == EPI_RES) {
                float2 r0 = *reinterpret_cast<const float2*>(&aux[(size_t)m * ldc + n]);
                float2 r1 = *reinterpret_cast<const float2*>(&aux[(size_t)(m + 8) * ldc + n]);
                v0.x += r0.x; v0.y += r0.y; v1.x += r1.x; v1.y += r1.y;
            }
            *reinterpret_cast<float2*>(&C[(size_t)m * ldc + n]) = v0;
            *reinterpret_cast<float2*>(&C[(size_t)(m + 8) * ldc + n]) = v1;
        }
    }
}

// ---------------------------------------------------------------------------
// Split-K reduce -> g_xdbl (fp32, for scan) + g_xdbl_h (fp16, for dt GEMM)
// ---------------------------------------------------------------------------
__global__ __launch_bounds__(256)
void xdbl_reduce_kernel()
{
    const int i = blockIdx.x * 256 + threadIdx.x;
    const int n4 = MROWS * XDBLC / 4;
    if (i >= n4) return;
    const float4* p = reinterpret_cast<const float4*>(g_xpart);
    float4 a0 = p[i],          a1 = p[i + n4],     a2 = p[i + 2 * n4], a3 = p[i + 3 * n4];
    float4 a4 = p[i + 4 * n4], a5 = p[i + 5 * n4], a6 = p[i + 6 * n4], a7 = p[i + 7 * n4];
    float4 r;
    r.x = ((a0.x + a1.x) + (a2.x + a3.x)) + ((a4.x + a5.x) + (a6.x + a7.x));
    r.y = ((a0.y + a1.y) + (a2.y + a3.y)) + ((a4.y + a5.y) + (a6.y + a7.y));
    r.z = ((a0.z + a1.z) + (a2.z + a3.z)) + ((a4.z + a5.z) + (a6.z + a7.z));
    r.w = ((a0.w + a1.w) + (a2.w + a3.w)) + ((a4.w + a5.w) + (a6.w + a7.w));
    reinterpret_cast<float4*>(g_xdbl)[i] = r;
    uint2 o;
    o.x = h2u(__floats2half2_rn(r.x, r.y));
    o.y = h2u(__floats2half2_rn(r.z, r.w));
    reinterpret_cast<uint2*>(g_xdbl_h)[i] = o;
}

// ---------------------------------------------------------------------------
// Depthwise causal conv (width 4) + SiLU -> g_xc_h (fp16 only)
// ---------------------------------------------------------------------------
__global__ __launch_bounds__(256)
void conv_silu_kernel(const float* __restrict__ conv_w,
                      const float* __restrict__ conv_b)
{
    int idx = blockIdx.x * 256 + threadIdx.x;
    if (idx >= MROWS * DINNER) return;
    int d = idx & (DINNER - 1);
    int m = idx >> 11;
    int l = m & (SEQ - 1);
    int brow = m - l;
    float s = conv_b[d];
#pragma unroll
    for (int j = 0; j < DCONV; j++) {
        int ll = l + j - (DCONV - 1);
        if (ll >= 0)
            s = fmaf(conv_w[d * DCONV + j], g_xz[(size_t)(brow + ll) * XZCOLS + d], s);
    }
    float v = s * (1.f / (1.f + __expf(-s)));
    g_xc_h[idx] = __float2half_rn(v);
}

// ---------------------------------------------------------------------------
// SMEM-staged selective scan; xc read as fp16, y written as fp16
// ---------------------------------------------------------------------------
#define TC 64
__global__ __launch_bounds__(256)
void scan_kernel(const float* __restrict__ A_log,
                 const float* __restrict__ Dvec)
{
    __shared__ __align__(16) float dt_s[TC][16];
    __shared__ __align__(16) float xc_s[TC][16];
    __shared__ __align__(16) float z_s [TC][16];
    __shared__ __align__(16) float B_s [TC][16];
    __shared__ __align__(16) float C_s [TC][16];
    __shared__ __align__(16) float y_s [TC][16];

    const int tid = threadIdx.x;
    const int s   = tid & 15;
    const int c   = tid >> 4;
    const int d0  = (blockIdx.x * 16) & (DINNER - 1);
    const int b   = (blockIdx.x * 16) >> 11;
    const int d   = d0 + c;

    const float As = -__expf(A_log[d * DSTATE + s]);
    const float Dd = Dvec[d];

    const int r = tid >> 2, q = tid & 3;
    const size_t mb = (size_t)b * SEQ;

    float4 p_dt, p_z, p_B, p_C;
    uint2  p_xc;
    auto ldg_chunk = [&](int t0) {
        size_t m = mb + t0 + r;
        p_dt = *reinterpret_cast<const float4*>(&g_dt  [m * DINNER + d0 + q * 4]);
        p_xc = *reinterpret_cast<const uint2*>(&g_xc_h [m * DINNER + d0 + q * 4]);
        p_z  = *reinterpret_cast<const float4*>(&g_xz  [m * XZCOLS + DINNER + d0 + q * 4]);
        p_B  = *reinterpret_cast<const float4*>(&g_xdbl[m * XDBLC + DTRANK + q * 4]);
        p_C  = *reinterpret_cast<const float4*>(&g_xdbl[m * XDBLC + DTRANK + DSTATE + q * 4]);
    };
    auto sts_chunk = [&]() {
        *reinterpret_cast<float4*>(&dt_s[r][q * 4]) = p_dt;
        __half2 h0 = *reinterpret_cast<__half2*>(&p_xc.x);
        __half2 h1 = *reinterpret_cast<__half2*>(&p_xc.y);
        float2 f0 = __half22float2(h0);
        float2 f1 = __half22float2(h1);
        *reinterpret_cast<float4*>(&xc_s[r][q * 4]) =
            make_float4(f0.x, f0.y, f1.x, f1.y);
        *reinterpret_cast<float4*>(&z_s [r][q * 4]) = p_z;
        *reinterpret_cast<float4*>(&B_s [r][q * 4]) = p_B;
        *reinterpret_cast<float4*>(&C_s [r][q * 4]) = p_C;
    };

    ldg_chunk(0);
    sts_chunk();
    __syncthreads();

    float h = 0.f;
    for (int t0 = 0; t0 < SEQ; t0 += TC) {
        if (t0 + TC < SEQ) ldg_chunk(t0 + TC);
#pragma unroll 4
        for (int t = 0; t < TC; t++) {
            float dt_v = dt_s[t][c];
            float x_v  = xc_s[t][c];
            float Bv   = B_s [t][s];
            float Cv   = C_s [t][s];
            float dA = __expf(dt_v * As);
            h = fmaf(dA, h, dt_v * Bv * x_v);
            float p = h * Cv;
            p += __shfl_xor_sync(0xffffffffu, p, 1);
            p += __shfl_xor_sync(0xffffffffu, p, 2);
            p += __shfl_xor_sync(0xffffffffu, p, 4);
            p += __shfl_xor_sync(0xffffffffu, p, 8);
            if (s == 0) {
                float zv = z_s[t][c];
                float y  = fmaf(Dd, x_v, p);
                y *= zv * (1.f / (1.f + __expf(-zv)));
                y_s[t][c] = y;
            }
        }
        __syncthreads();
        {
            size_t m = mb + t0 + r;
            float4 yv = *reinterpret_cast<const float4*>(&y_s[r][q * 4]);
            uint2 o;
            o.x = h2u(__floats2half2_rn(yv.x, yv.y));
            o.y = h2u(__floats2half2_rn(yv.z, yv.w));
            *reinterpret_cast<uint2*>(&g_y_h[m * DINNER + d0 + q * 4]) = o;
        }
        if (t0 + TC < SEQ) sts_chunk();
        __syncthreads();
    }
}

// ---------------------------------------------------------------------------
// LayerNorm
// ---------------------------------------------------------------------------
__global__ __launch_bounds__(256)
void ln_kernel(const float* __restrict__ h,
               const float* __restrict__ gamma,
               const float* __restrict__ beta,
               float* __restrict__ out)
{
    int m = blockIdx.x;
    const float* row = h + (size_t)m * DMODEL;
    float s = 0.f, s2 = 0.f;
    for (int i = threadIdx.x; i < DMODEL; i += 256) {
        float v = row[i];
        s += v;
        s2 = fmaf(v, v, s2);
    }
#pragma unroll
    for (int o = 16; o; o >>= 1) {
        s  += __shfl_xor_sync(0xffffffffu, s,  o);
        s2 += __shfl_xor_sync(0xffffffffu, s2, o);
    }
    __shared__ float ss[8], ss2[8];
    int w = threadIdx.x >> 5, ln = threadIdx.x & 31;
    if (ln == 0) { ss[w] = s; ss2[w] = s2; }
    __syncthreads();
    s = 0.f; s2 = 0.f;
#pragma unroll
    for (int i = 0; i < 8; i++) { s += ss[i]; s2 += ss2[i]; }
    float mu  = s * (1.f / DMODEL);
    float var = s2 * (1.f / DMODEL) - mu * mu;
    float inv = rsqrtf(var + 1e-5f);
    for (int i = threadIdx.x; i < DMODEL; i += 256) {
        float v = row[i];
        out[(size_t)m * DMODEL + i] = (v - mu) * inv * gamma[i] + beta[i];
    }
}

// ---------------------------------------------------------------------------
// Launch
// ---------------------------------------------------------------------------
extern "C" void kernel_launch(void* const* d_in, const int* in_sizes, int n_in,
                              void* d_out, int out_size)
{
    const float* x          = (const float*)d_in[0];
    const float* in_proj_w  = (const float*)d_in[1];
    const float* conv_w     = (const float*)d_in[2];
    const float* conv_b     = (const float*)d_in[3];
    const float* x_proj_w   = (const float*)d_in[4];
    const float* dt_proj_w  = (const float*)d_in[5];
    const float* dt_proj_b  = (const float*)d_in[6];
    const float* A_log      = (const float*)d_in[7];
    const float* Dvec       = (const float*)d_in[8];
    const float* out_proj_w = (const float*)d_in[9];
    const float* ln_gamma   = (const float*)d_in[10];
    const float* ln_beta    = (const float*)d_in[11];
    float* out = (float*)d_out;

    float  *p_xz, *p_xpart, *p_dt, *p_h;
    __half *p_xch, *p_xdblh, *p_yh, *p_xh, *p_winh, *p_wouth, *p_wxh, *p_wdth;
    cudaGetSymbolAddress((void**)&p_xz,    g_xz);
    cudaGetSymbolAddress((void**)&p_xch,   g_xc_h);
    cudaGetSymbolAddress((void**)&p_xdblh, g_xdbl_h);
    cudaGetSymbolAddress((void**)&p_xpart, g_xpart);
    cudaGetSymbolAddress((void**)&p_dt,    g_dt);
    cudaGetSymbolAddress((void**)&p_yh,    g_y_h);
    cudaGetSymbolAddress((void**)&p_h,     g_h);
    cudaGetSymbolAddress((void**)&p_xh,    g_x_h);
    cudaGetSymbolAddress((void**)&p_winh,  g_win_h);
    cudaGetSymbolAddress((void**)&p_wouth, g_wout_h);
    cudaGetSymbolAddress((void**)&p_wxh,   g_wx_h);
    cudaGetSymbolAddress((void**)&p_wdth,  g_wdt_h);

    const int SMEM = GSTAGES * (16384 + 16384);   // 96 KB
    cudaFuncSetAttribute(hmma_gemm_nt<EPI_PLAIN>,
                         cudaFuncAttributeMaxDynamicSharedMemorySize, SMEM);
    cudaFuncSetAttribute(hmma_gemm_nt<EPI_SOFTPLUS>,
                         cudaFuncAttributeMaxDynamicSharedMemorySize, SMEM);
    cudaFuncSetAttribute(hmma_gemm_nt<EPI_RES>,
                         cudaFuncAttributeMaxDynamicSharedMemorySize, SMEM);

    // 1-3) fp16 conversions needed by in_proj (in_proj lands 4th = ncu slot)
    cvt_half_kernel<<<MROWS * DMODEL / 4 / 256, 256>>>(
        (const float4*)x, (uint2*)p_xh, MROWS * DMODEL / 4);
    cvt_half_kernel<<<XZCOLS * DMODEL / 4 / 256, 256>>>(
        (const float4*)in_proj_w, (uint2*)p_winh, XZCOLS * DMODEL / 4);
    cvt_half_kernel<<<DMODEL * DINNER / 4 / 256, 256>>>(
        (const float4*)out_proj_w, (uint2*)p_wouth, DMODEL * DINNER / 4);

    // 4) in_proj: xz = x @ W_in^T   (4096 x 4096, K=1024)
    hmma_gemm_nt<EPI_PLAIN><<<dim3(XZCOLS / 128, MROWS / 128, 1), 256, SMEM>>>(
        p_xh, DMODEL, p_winh, DMODEL, p_xz, XZCOLS,
        DMODEL, XZCOLS, nullptr, 0, 0);

    // 5-6) remaining weight conversions
    cvt_half_kernel<<<XDBLC * DINNER / 4 / 256, 256>>>(
        (const float4*)x_proj_w, (uint2*)p_wxh, XDBLC * DINNER / 4);
    cvt_half_kernel<<<DINNER * DTRANK / 4 / 256, 256>>>(
        (const float4*)dt_proj_w, (uint2*)p_wdth, DINNER * DTRANK / 4);

    // 7) conv + silu -> g_xc_h (fp16)
    conv_silu_kernel<<<(MROWS * DINNER + 255) / 256, 256>>>(conv_w, conv_b);

    // 8) x_proj (split-K=8): xc @ W_x^T  (4096 x 96, K=2048)
    hmma_gemm_nt<EPI_PLAIN><<<dim3(1, MROWS / 128, XSPLITK), 256, SMEM>>>(
        p_xch, DINNER, p_wxh, DINNER, p_xpart, XDBLC,
        DINNER / XSPLITK, XDBLC, nullptr,
        DINNER / XSPLITK, (size_t)MROWS * XDBLC);

    // 9) reduce partials -> g_xdbl (+ fp16 copy)
    xdbl_reduce_kernel<<<(MROWS * XDBLC / 4 + 255) / 256, 256>>>();

    // 10) dt = softplus(x_dbl[:, :64] @ W_dt^T + b)  (4096 x 2048, K=64)
    hmma_gemm_nt<EPI_SOFTPLUS><<<dim3(DINNER / 128, MROWS / 128, 1), 256, SMEM>>>(
        p_xdblh, XDBLC, p_wdth, DTRANK, p_dt, DINNER,
        DTRANK, DINNER, dt_proj_b, 0, 0);

    // 11) selective scan (+ D-skip, * silu(z)) -> g_y_h
    scan_kernel<<<(BATCH * DINNER) / 16, 256>>>(A_log, Dvec);

    // 12) out_proj + residual: h = y @ W_out^T + x   (4096 x 1024, K=2048)
    hmma_gemm_nt<EPI_RES><<<dim3(DMODEL / 128, MROWS / 128, 1), 256, SMEM>>>(
        p_yh, DINNER, p_wouth, DINNER, p_h, DMODEL,
        DINNER, DMODEL, x, 0, 0);

    // 13) LayerNorm -> out
    ln_kernel<<<MROWS, 256>>>(p_h, ln_gamma, ln_beta, out);
}

// round 17
// speedup vs baseline: 1.3951x; 1.0222x over previous
// R17: fp16 xz + dt streams (HOUT epilogues); GEMM mainloop unchanged from R16.
#include <cuda_runtime.h>
#include <cuda_fp16.h>
#include <cstdint>

#define BATCH   2
#define SEQ     2048
#define DMODEL  1024
#define DINNER  2048
#define DSTATE  16
#define DCONV   4
#define DTRANK  64
#define MROWS   (BATCH * SEQ)          // 4096
#define XZCOLS  (2 * DINNER)           // 4096
#define XDBLC   (DTRANK + 2 * DSTATE)  // 96
#define XSPLITK 8

// ---------------------------------------------------------------------------
// Scratch (device globals)
// ---------------------------------------------------------------------------
__device__ __half g_xz_h  [(size_t)MROWS * XZCOLS];   // [xi | z] fp16
__device__ __half g_xc_h  [(size_t)MROWS * DINNER];   // conv+silu fp16
__device__ float  g_xdbl  [(size_t)MROWS * XDBLC];    // [dt_r | B | C] fp32 (scan)
__device__ __half g_xdbl_h[(size_t)MROWS * XDBLC];    // fp16 copy (dt A)
__device__ float  g_xpart [(size_t)XSPLITK * MROWS * XDBLC];
__device__ __half g_dt_h  [(size_t)MROWS * DINNER];   // softplus(dt) fp16
__device__ __half g_y_h   [(size_t)MROWS * DINNER];   // scan out fp16
__device__ float  g_h     [(size_t)MROWS * DMODEL];   // out_proj + residual
// fp16 operands
__device__ __half g_x_h   [(size_t)MROWS * DMODEL];
__device__ __half g_win_h [(size_t)XZCOLS * DMODEL];
__device__ __half g_wout_h[(size_t)DMODEL * DINNER];
__device__ __half g_wx_h  [(size_t)XDBLC * DINNER];
__device__ __half g_wdt_h [(size_t)DINNER * DTRANK];

enum { EPI_PLAIN = 0, EPI_SOFTPLUS = 1, EPI_RES = 2 };

// ---------------------------------------------------------------------------
// PTX helpers
// ---------------------------------------------------------------------------
__device__ __forceinline__ void cp_async16(uint32_t dst, const void* src) {
    asm volatile("cp.async.cg.shared.global [%0], [%1], 16;\n" :: "r"(dst), "l"(src));
}
__device__ __forceinline__ void cp_commit() {
    asm volatile("cp.async.commit_group;\n" ::: "memory");
}
template <int N> __device__ __forceinline__ void cp_wait() {
    asm volatile("cp.async.wait_group %0;\n" :: "n"(N) : "memory");
}
__device__ __forceinline__ void ldsm_x4(uint32_t& r0, uint32_t& r1,
                                        uint32_t& r2, uint32_t& r3, uint32_t addr) {
    asm volatile("ldmatrix.sync.aligned.m8n8.x4.shared.b16 {%0,%1,%2,%3}, [%4];\n"
                 : "=r"(r0), "=r"(r1), "=r"(r2), "=r"(r3) : "r"(addr));
}
__device__ __forceinline__ uint32_t h2u(__half2 h) {
    return *reinterpret_cast<uint32_t*>(&h);
}

// ---------------------------------------------------------------------------
// fp32 -> fp16 (rne) conversion kernel
// ---------------------------------------------------------------------------
__global__ __launch_bounds__(256)
void cvt_half_kernel(const float4* __restrict__ src, uint2* __restrict__ dst, int n4)
{
    int i = blockIdx.x * 256 + threadIdx.x;
    if (i >= n4) return;
    float4 v = src[i];
    uint2 o;
    o.x = h2u(__floats2half2_rn(v.x, v.y));
    o.y = h2u(__floats2half2_rn(v.z, v.w));
    dst[i] = o;
}

// ---------------------------------------------------------------------------
// fp16 tensor-core NT GEMM: C[M,N] = A[M,K]*B[N,K]^T, fp32 accum.
// HOUT=false: fp32 C; HOUT=true: fp16 C (half2 stores).
// BM=128, BN=128, BK=64, SW128 swizzle, 3-stage cp.async, ldmatrix.x4,
// mma.sync.m16n8k16. 256 thr = 8 warps (4m x 2n), warp tile 32x64.
// launch_bounds(256,2) -> 2 CTAs/SM. M%128==0, K%64==0; N<128 handled.
// ---------------------------------------------------------------------------
#define GSTAGES 3
template <int EPI, bool HOUT>
__global__ __launch_bounds__(256, 2)
void hmma_gemm_nt(const __half* __restrict__ A, int lda,
                  const __half* __restrict__ B, int ldb,
                  void* __restrict__ Cv, int ldc,
                  int K, int N, const float* __restrict__ aux,
                  int kz, size_t cz)
{
    constexpr int BK = 64;
    constexpr int T_BYTES = 128 * BK * 2;    // 16 KB per operand tile
    extern __shared__ __align__(16) char smem[];
    const uint32_t smem_u = (uint32_t)__cvta_generic_to_shared(smem);
    const uint32_t smA = smem_u;
    const uint32_t smB = smem_u + GSTAGES * T_BYTES;

    A += (size_t)blockIdx.z * kz;
    B += (size_t)blockIdx.z * kz;
    float*  Cf = reinterpret_cast<float*>(Cv)  + (HOUT ? 0 : (size_t)blockIdx.z * cz);
    __half* Ch = reinterpret_cast<__half*>(Cv) + (HOUT ? (size_t)blockIdx.z * cz : 0);

    const int tid  = threadIdx.x, lane = tid & 31, wid = tid >> 5;
    const int g    = lane >> 2, tig = lane & 3;
    const int wm   = wid & 3, wn = wid >> 2;
    const int m0   = blockIdx.y * 128, n0 = blockIdx.x * 128;

    const __half* asrc[4]; const __half* bsrc[4]; uint32_t soff[4];
#pragma unroll
    for (int i = 0; i < 4; i++) {
        int id = tid + i * 256, r = id >> 3, ch = id & 7;
        soff[i] = (uint32_t)((r * 128 + ch * 16) ^ ((r & 7) << 4));
        asrc[i] = A + (size_t)(m0 + r) * lda + ch * 8;
        int br = n0 + r; if (br > N - 1) br = N - 1;
        bsrc[i] = B + (size_t)br * ldb + ch * 8;
    }

    const int lrow  = (lane & 7) + ((lane >> 3) & 1) * 8;
    const int lkb   = ((lane >> 4) & 1) * 16;
    const uint32_t lmask = (uint32_t)((lane & 7) << 4);
    uint32_t abase[2], bbase[4];
#pragma unroll
    for (int mi = 0; mi < 2; mi++)
        abase[mi] = (uint32_t)((wm * 32 + mi * 16 + lrow) * 128 + lkb);
#pragma unroll
    for (int p = 0; p < 4; p++)
        bbase[p] = (uint32_t)((wn * 64 + p * 16 + lrow) * 128 + lkb);

    float acc[2][8][4];
#pragma unroll
    for (int mi = 0; mi < 2; mi++)
#pragma unroll
        for (int nj = 0; nj < 8; nj++)
#pragma unroll
            for (int q = 0; q < 4; q++) acc[mi][nj][q] = 0.f;

    const int NK = K / BK;
    auto issue = [&](int t) {
        const int s = t % GSTAGES;
        const uint32_t sa = smA + s * T_BYTES;
        const uint32_t sB = smB + s * T_BYTES;
        const int k0 = t * BK;
#pragma unroll
        for (int i = 0; i < 4; i++) {
            cp_async16(sa + soff[i], asrc[i] + k0);
            cp_async16(sB + soff[i], bsrc[i] + k0);
        }
    };

    issue(0); cp_commit();
    if (NK > 1) issue(1);
    cp_commit();

    for (int t = 0; t < NK; t++) {
        if (t + 1 < NK) cp_wait<1>(); else cp_wait<0>();
        __syncthreads();
        if (t + 2 < NK) issue(t + 2);
        cp_commit();

        const int s = t % GSTAGES;
        const uint32_t sa = smA + s * T_BYTES;
        const uint32_t sB = smB + s * T_BYTES;

#pragma unroll
        for (int kg = 0; kg < 4; kg++) {
            uint32_t af[2][4];
#pragma unroll
            for (int mi = 0; mi < 2; mi++)
                ldsm_x4(af[mi][0], af[mi][1], af[mi][2], af[mi][3],
                        sa + ((abase[mi] + kg * 32) ^ lmask));
            uint32_t bf[8][2];
#pragma unroll
            for (int p = 0; p < 4; p++) {
                uint32_t r0, r1, r2, r3;
                ldsm_x4(r0, r1, r2, r3, sB + ((bbase[p] + kg * 32) ^ lmask));
                bf[2 * p][0] = r0; bf[2 * p + 1][0] = r1;
                bf[2 * p][1] = r2; bf[2 * p + 1][1] = r3;
            }
#pragma unroll
            for (int mi = 0; mi < 2; mi++)
#pragma unroll
                for (int nj = 0; nj < 8; nj++) {
                    asm volatile(
                        "mma.sync.aligned.m16n8k16.row.col.f32.f16.f16.f32 "
                        "{%0,%1,%2,%3}, {%4,%5,%6,%7}, {%8,%9}, {%0,%1,%2,%3};\n"
                        : "+f"(acc[mi][nj][0]), "+f"(acc[mi][nj][1]),
                          "+f"(acc[mi][nj][2]), "+f"(acc[mi][nj][3])
                        : "r"(af[mi][0]), "r"(af[mi][1]), "r"(af[mi][2]), "r"(af[mi][3]),
                          "r"(bf[nj][0]), "r"(bf[nj][1]));
                }
        }
    }

    // ---- epilogue ----
#pragma unroll
    for (int mi = 0; mi < 2; mi++) {
#pragma unroll
        for (int nj = 0; nj < 8; nj++) {
            int m = m0 + wm * 32 + mi * 16 + g;
            int n = n0 + wn * 64 + nj * 8 + 2 * tig;
            if (n >= N) continue;
            float2 v0 = make_float2(acc[mi][nj][0], acc[mi][nj][1]);  // row m
            float2 v1 = make_float2(acc[mi][nj][2], acc[mi][nj][3]);  // row m+8
            if (EPI == EPI_SOFTPLUS) {
                float b0 = aux[n], b1 = aux[n + 1];
                v0.x += b0; v0.y += b1; v1.x += b0; v1.y += b1;
                v0.x = (v0.x > 20.f) ? v0.x : log1pf(__expf(v0.x));
                v0.y = (v0.y > 20.f) ? v0.y : log1pf(__expf(v0.y));
                v1.x = (v1.x > 20.f) ? v1.x : log1pf(__expf(v1.x));
                v1.y = (v1.y > 20.f) ? v1.y : log1pf(__expf(v1.y));
            } else if (EPI == EPI_RES) {
                float2 r0 = *reinterpret_cast<const float2*>(&aux[(size_t)m * ldc + n]);
                float2 r1 = *reinterpret_cast<const float2*>(&aux[(size_t)(m + 8) * ldc + n]);
                v0.x += r0.x; v0.y += r0.y; v1.x += r1.x; v1.y += r1.y;
            }
            if (HOUT) {
                *reinterpret_cast<uint32_t*>(&Ch[(size_t)m * ldc + n]) =
                    h2u(__floats2half2_rn(v0.x, v0.y));
                *reinterpret_cast<uint32_t*>(&Ch[(size_t)(m + 8) * ldc + n]) =
                    h2u(__floats2half2_rn(v1.x, v1.y));
            } else {
                *reinterpret_cast<float2*>(&Cf[(size_t)m * ldc + n]) = v0;
                *reinterpret_cast<float2*>(&Cf[(size_t)(m + 8) * ldc + n]) = v1;
            }
        }
    }
}

// ---------------------------------------------------------------------------
// Split-K reduce -> g_xdbl (fp32, scan) + g_xdbl_h (fp16, dt GEMM)
// ---------------------------------------------------------------------------
__global__ __launch_bounds__(256)
void xdbl_reduce_kernel()
{
    const int i = blockIdx.x * 256 + threadIdx.x;
    const int n4 = MROWS * XDBLC / 4;
    if (i >= n4) return;
    const float4* p = reinterpret_cast<const float4*>(g_xpart);
    float4 a0 = p[i],          a1 = p[i + n4],     a2 = p[i + 2 * n4], a3 = p[i + 3 * n4];
    float4 a4 = p[i + 4 * n4], a5 = p[i + 5 * n4], a6 = p[i + 6 * n4], a7 = p[i + 7 * n4];
    float4 r;
    r.x = ((a0.x + a1.x) + (a2.x + a3.x)) + ((a4.x + a5.x) + (a6.x + a7.x));
    r.y = ((a0.y + a1.y) + (a2.y + a3.y)) + ((a4.y + a5.y) + (a6.y + a7.y));
    r.z = ((a0.z + a1.z) + (a2.z + a3.z)) + ((a4.z + a5.z) + (a6.z + a7.z));
    r.w = ((a0.w + a1.w) + (a2.w + a3.w)) + ((a4.w + a5.w) + (a6.w + a7.w));
    reinterpret_cast<float4*>(g_xdbl)[i] = r;
    uint2 o;
    o.x = h2u(__floats2half2_rn(r.x, r.y));
    o.y = h2u(__floats2half2_rn(r.z, r.w));
    reinterpret_cast<uint2*>(g_xdbl_h)[i] = o;
}

// ---------------------------------------------------------------------------
// Depthwise causal conv (width 4) + SiLU: xi fp16 -> g_xc_h fp16
// ---------------------------------------------------------------------------
__global__ __launch_bounds__(256)
void conv_silu_kernel(const float* __restrict__ conv_w,
                      const float* __restrict__ conv_b)
{
    int idx = blockIdx.x * 256 + threadIdx.x;
    if (idx >= MROWS * DINNER) return;
    int d = idx & (DINNER - 1);
    int m = idx >> 11;
    int l = m & (SEQ - 1);
    int brow = m - l;
    float s = conv_b[d];
#pragma unroll
    for (int j = 0; j < DCONV; j++) {
        int ll = l + j - (DCONV - 1);
        if (ll >= 0)
            s = fmaf(conv_w[d * DCONV + j],
                     __half2float(g_xz_h[(size_t)(brow + ll) * XZCOLS + d]), s);
    }
    float v = s * (1.f / (1.f + __expf(-s)));
    g_xc_h[idx] = __float2half_rn(v);
}

// ---------------------------------------------------------------------------
// SMEM-staged selective scan; dt/xc/z read fp16, y written fp16
// ---------------------------------------------------------------------------
#define TC 64
__global__ __launch_bounds__(256)
void scan_kernel(const float* __restrict__ A_log,
                 const float* __restrict__ Dvec)
{
    __shared__ __align__(16) float dt_s[TC][16];
    __shared__ __align__(16) float xc_s[TC][16];
    __shared__ __align__(16) float z_s [TC][16];
    __shared__ __align__(16) float B_s [TC][16];
    __shared__ __align__(16) float C_s [TC][16];
    __shared__ __align__(16) float y_s [TC][16];

    const int tid = threadIdx.x;
    const int s   = tid & 15;
    const int c   = tid >> 4;
    const int d0  = (blockIdx.x * 16) & (DINNER - 1);
    const int b   = (blockIdx.x * 16) >> 11;
    const int d   = d0 + c;

    const float As = -__expf(A_log[d * DSTATE + s]);
    const float Dd = Dvec[d];

    const int r = tid >> 2, q = tid & 3;
    const size_t mb = (size_t)b * SEQ;

    uint2  p_dt, p_xc, p_z;
    float4 p_B, p_C;
    auto ldg_chunk = [&](int t0) {
        size_t m = mb + t0 + r;
        p_dt = *reinterpret_cast<const uint2*>(&g_dt_h[m * DINNER + d0 + q * 4]);
        p_xc = *reinterpret_cast<const uint2*>(&g_xc_h[m * DINNER + d0 + q * 4]);
        p_z  = *reinterpret_cast<const uint2*>(&g_xz_h[m * XZCOLS + DINNER + d0 + q * 4]);
        p_B  = *reinterpret_cast<const float4*>(&g_xdbl[m * XDBLC + DTRANK + q * 4]);
        p_C  = *reinterpret_cast<const float4*>(&g_xdbl[m * XDBLC + DTRANK + DSTATE + q * 4]);
    };
    auto cvt4 = [](uint2 u) {
        __half2 h0 = *reinterpret_cast<__half2*>(&u.x);
        __half2 h1 = *reinterpret_cast<__half2*>(&u.y);
        float2 f0 = __half22float2(h0);
        float2 f1 = __half22float2(h1);
        return make_float4(f0.x, f0.y, f1.x, f1.y);
    };
    auto sts_chunk = [&]() {
        *reinterpret_cast<float4*>(&dt_s[r][q * 4]) = cvt4(p_dt);
        *reinterpret_cast<float4*>(&xc_s[r][q * 4]) = cvt4(p_xc);
        *reinterpret_cast<float4*>(&z_s [r][q * 4]) = cvt4(p_z);
        *reinterpret_cast<float4*>(&B_s [r][q * 4]) = p_B;
        *reinterpret_cast<float4*>(&C_s [r][q * 4]) = p_C;
    };

    ldg_chunk(0);
    sts_chunk();
    __syncthreads();

    float h = 0.f;
    for (int t0 = 0; t0 < SEQ; t0 += TC) {
        if (t0 + TC < SEQ) ldg_chunk(t0 + TC);
#pragma unroll 4
        for (int t = 0; t < TC; t++) {
            float dt_v = dt_s[t][c];
            float x_v  = xc_s[t][c];
            float Bv   = B_s [t][s];
            float Cv   = C_s [t][s];
            float dA = __expf(dt_v * As);
            h = fmaf(dA, h, dt_v * Bv * x_v);
            float p = h * Cv;
            p += __shfl_xor_sync(0xffffffffu, p, 1);
            p += __shfl_xor_sync(0xffffffffu, p, 2);
            p += __shfl_xor_sync(0xffffffffu, p, 4);
            p += __shfl_xor_sync(0xffffffffu, p, 8);
            if (s == 0) {
                float zv = z_s[t][c];
                float y  = fmaf(Dd, x_v, p);
                y *= zv * (1.f / (1.f + __expf(-zv)));
                y_s[t][c] = y;
            }
        }
        __syncthreads();
        {
            size_t m = mb + t0 + r;
            float4 yv = *reinterpret_cast<const float4*>(&y_s[r][q * 4]);
            uint2 o;
            o.x = h2u(__floats2half2_rn(yv.x, yv.y));
            o.y = h2u(__floats2half2_rn(yv.z, yv.w));
            *reinterpret_cast<uint2*>(&g_y_h[m * DINNER + d0 + q * 4]) = o;
        }
        if (t0 + TC < SEQ) sts_chunk();
        __syncthreads();
    }
}

// ---------------------------------------------------------------------------
// LayerNorm
// ---------------------------------------------------------------------------
__global__ __launch_bounds__(256)
void ln_kernel(const float* __restrict__ h,
               const float* __restrict__ gamma,
               const float* __restrict__ beta,
               float* __restrict__ out)
{
    int m = blockIdx.x;
    const float* row = h + (size_t)m * DMODEL;
    float s = 0.f, s2 = 0.f;
    for (int i = threadIdx.x; i < DMODEL; i += 256) {
        float v = row[i];
        s += v;
        s2 = fmaf(v, v, s2);
    }
#pragma unroll
    for (int o = 16; o; o >>= 1) {
        s  += __shfl_xor_sync(0xffffffffu, s,  o);
        s2 += __shfl_xor_sync(0xffffffffu, s2, o);
    }
    __shared__ float ss[8], ss2[8];
    int w = threadIdx.x >> 5, ln = threadIdx.x & 31;
    if (ln == 0) { ss[w] = s; ss2[w] = s2; }
    __syncthreads();
    s = 0.f; s2 = 0.f;
#pragma unroll
    for (int i = 0; i < 8; i++) { s += ss[i]; s2 += ss2[i]; }
    float mu  = s * (1.f / DMODEL);
    float var = s2 * (1.f / DMODEL) - mu * mu;
    float inv = rsqrtf(var + 1e-5f);
    for (int i = threadIdx.x; i < DMODEL; i += 256) {
        float v = row[i];
        out[(size_t)m * DMODEL + i] = (v - mu) * inv * gamma[i] + beta[i];
    }
}

// ---------------------------------------------------------------------------
// Launch
// ---------------------------------------------------------------------------
extern "C" void kernel_launch(void* const* d_in, const int* in_sizes, int n_in,
                              void* d_out, int out_size)
{
    const float* x          = (const float*)d_in[0];
    const float* in_proj_w  = (const float*)d_in[1];
    const float* conv_w     = (const float*)d_in[2];
    const float* conv_b     = (const float*)d_in[3];
    const float* x_proj_w   = (const float*)d_in[4];
    const float* dt_proj_w  = (const float*)d_in[5];
    const float* dt_proj_b  = (const float*)d_in[6];
    const float* A_log      = (const float*)d_in[7];
    const float* Dvec       = (const float*)d_in[8];
    const float* out_proj_w = (const float*)d_in[9];
    const float* ln_gamma   = (const float*)d_in[10];
    const float* ln_beta    = (const float*)d_in[11];
    float* out = (float*)d_out;

    float  *p_xpart, *p_h;
    __half *p_xzh, *p_xch, *p_xdblh, *p_dth, *p_yh, *p_xh, *p_winh, *p_wouth, *p_wxh, *p_wdth;
    cudaGetSymbolAddress((void**)&p_xzh,   g_xz_h);
    cudaGetSymbolAddress((void**)&p_xch,   g_xc_h);
    cudaGetSymbolAddress((void**)&p_xdblh, g_xdbl_h);
    cudaGetSymbolAddress((void**)&p_xpart, g_xpart);
    cudaGetSymbolAddress((void**)&p_dth,   g_dt_h);
    cudaGetSymbolAddress((void**)&p_yh,    g_y_h);
    cudaGetSymbolAddress((void**)&p_h,     g_h);
    cudaGetSymbolAddress((void**)&p_xh,    g_x_h);
    cudaGetSymbolAddress((void**)&p_winh,  g_win_h);
    cudaGetSymbolAddress((void**)&p_wouth, g_wout_h);
    cudaGetSymbolAddress((void**)&p_wxh,   g_wx_h);
    cudaGetSymbolAddress((void**)&p_wdth,  g_wdt_h);

    const int SMEM = GSTAGES * (16384 + 16384);   // 96 KB
    cudaFuncSetAttribute((const void*)hmma_gemm_nt<EPI_PLAIN, true>,
                         cudaFuncAttributeMaxDynamicSharedMemorySize, SMEM);
    cudaFuncSetAttribute((const void*)hmma_gemm_nt<EPI_PLAIN, false>,
                         cudaFuncAttributeMaxDynamicSharedMemorySize, SMEM);
    cudaFuncSetAttribute((const void*)hmma_gemm_nt<EPI_SOFTPLUS, true>,
                         cudaFuncAttributeMaxDynamicSharedMemorySize, SMEM);
    cudaFuncSetAttribute((const void*)hmma_gemm_nt<EPI_RES, false>,
                         cudaFuncAttributeMaxDynamicSharedMemorySize, SMEM);

    // 1-3) fp16 conversions needed by in_proj
    cvt_half_kernel<<<MROWS * DMODEL / 4 / 256, 256>>>(
        (const float4*)x, (uint2*)p_xh, MROWS * DMODEL / 4);
    cvt_half_kernel<<<XZCOLS * DMODEL / 4 / 256, 256>>>(
        (const float4*)in_proj_w, (uint2*)p_winh, XZCOLS * DMODEL / 4);
    cvt_half_kernel<<<DMODEL * DINNER / 4 / 256, 256>>>(
        (const float4*)out_proj_w, (uint2*)p_wouth, DMODEL * DINNER / 4);

    // 4) in_proj: xz = x @ W_in^T  -> fp16  (4096 x 4096, K=1024)
    hmma_gemm_nt<EPI_PLAIN, true><<<dim3(XZCOLS / 128, MROWS / 128, 1), 256, SMEM>>>(
        p_xh, DMODEL, p_winh, DMODEL, p_xzh, XZCOLS,
        DMODEL, XZCOLS, nullptr, 0, 0);

    // 5-6) remaining weight conversions
    cvt_half_kernel<<<XDBLC * DINNER / 4 / 256, 256>>>(
        (const float4*)x_proj_w, (uint2*)p_wxh, XDBLC * DINNER / 4);
    cvt_half_kernel<<<DINNER * DTRANK / 4 / 256, 256>>>(
        (const float4*)dt_proj_w, (uint2*)p_wdth, DINNER * DTRANK / 4);

    // 7) conv + silu -> g_xc_h (fp16)
    conv_silu_kernel<<<(MROWS * DINNER + 255) / 256, 256>>>(conv_w, conv_b);

    // 8) x_proj (split-K=8): xc @ W_x^T  (4096 x 96, K=2048) -> fp32 partials
    hmma_gemm_nt<EPI_PLAIN, false><<<dim3(1, MROWS / 128, XSPLITK), 256, SMEM>>>(
        p_xch, DINNER, p_wxh, DINNER, p_xpart, XDBLC,
        DINNER / XSPLITK, XDBLC, nullptr,
        DINNER / XSPLITK, (size_t)MROWS * XDBLC);

    // 9) reduce partials -> g_xdbl (+ fp16 copy)
    xdbl_reduce_kernel<<<(MROWS * XDBLC / 4 + 255) / 256, 256>>>();

    // 10) dt = softplus(x_dbl[:, :64] @ W_dt^T + b) -> fp16  (4096 x 2048, K=64)
    hmma_gemm_nt<EPI_SOFTPLUS, true><<<dim3(DINNER / 128, MROWS / 128, 1), 256, SMEM>>>(
        p_xdblh, XDBLC, p_wdth, DTRANK, p_dth, DINNER,
        DTRANK, DINNER, dt_proj_b, 0, 0);

    // 11) selective scan (+ D-skip, * silu(z)) -> g_y_h
    scan_kernel<<<(BATCH * DINNER) / 16, 256>>>(A_log, Dvec);

    // 12) out_proj + residual: h = y @ W_out^T + x  (4096 x 1024, K=2048)
    hmma_gemm_nt<EPI_RES, false><<<dim3(DMODEL / 128, MROWS / 128, 1), 256, SMEM>>>(
        p_yh, DINNER, p_wouth, DINNER, p_h, DMODEL,
        DINNER, DMODEL, x, 0, 0);

    // 13) LayerNorm -> out
    ln_kernel<<<MROWS, 256>>>(p_h, ln_gamma, ln_beta, out);
}